// round 11
// baseline (speedup 1.0000x reference)
#include <cuda_runtime.h>
#include <math.h>

#define BLOCK 128
// embed pass grid (6 CTAs/SM)
#define NBE 888
#define BJE 592
#define NBME 296
// read passes grid (8 CTAs/SM)
#define NBA 1184
#define BJA 790
#define NBMA 394
#define IMAXX 0x7fffffff
typedef unsigned long long u64;

__device__ float g_Ej[16000000];
__device__ float g_Em[8000000];
__device__ float g_pJ[BJA * 17], g_pM[NBMA * 17];
__device__ float g_aV[NBA]; __device__ int g_aI[NBA]; __device__ float g_aS[NBA];
__device__ float g_g1[16], g_g2[16], g_ejs[16];
__device__ float g_logpj; __device__ int g_selj;
__device__ int g_c0, g_c1, g_c2, g_c3;
__device__ int g_s0, g_s1, g_s2, g_s3, g_s4, g_s5;

// ---------- packed f32x2 + fast math ----------
__device__ __forceinline__ u64 F2(u64 a, u64 b, u64 c) {
    u64 r; asm("fma.rn.f32x2 %0,%1,%2,%3;" : "=l"(r) : "l"(a), "l"(b), "l"(c)); return r;
}
__device__ __forceinline__ u64 pack2(float lo, float hi) {
    u64 r; asm("mov.b64 %0,{%1,%2};" : "=l"(r) : "f"(lo), "f"(hi)); return r;
}
__device__ __forceinline__ float2 unpack2(u64 v) {
    float2 r; asm("mov.b64 {%0,%1},%2;" : "=f"(r.x), "=f"(r.y) : "l"(v)); return r;
}
__device__ __forceinline__ float ftanh(float x) {
    float r; asm("tanh.approx.f32 %0,%1;" : "=f"(r) : "f"(x)); return r;
}

// ---------- bulk-async + mbarrier ----------
__device__ __forceinline__ unsigned s2u(const void* p) { return (unsigned)__cvta_generic_to_shared(p); }
__device__ __forceinline__ void mb_init(unsigned a, unsigned c) {
    asm volatile("mbarrier.init.shared.b64 [%0], %1;" :: "r"(a), "r"(c) : "memory");
}
__device__ __forceinline__ void mb_tx(unsigned a, unsigned bytes) {
    asm volatile("mbarrier.arrive.expect_tx.shared.b64 _, [%0], %1;" :: "r"(a), "r"(bytes) : "memory");
}
__device__ __forceinline__ void mb_wait(unsigned a, unsigned p) {
    asm volatile(
        "{\n\t.reg .pred P;\n"
        "WL%=:\n\t"
        "mbarrier.try_wait.parity.acquire.cta.shared::cta.b64 P, [%0], %1, 0x989680;\n\t"
        "@P bra WD%=;\n\t"
        "bra WL%=;\n"
        "WD%=:\n\t}"
        :: "r"(a), "r"(p) : "memory");
}
__device__ __forceinline__ void bulk_g2s(unsigned dst, const void* src, unsigned sz, unsigned mb) {
    asm volatile("cp.async.bulk.shared::cluster.global.mbarrier::complete_tx::bytes [%0], [%1], %2, [%3];"
                 :: "r"(dst), "l"(src), "r"(sz), "r"(mb) : "memory");
}
__device__ __forceinline__ void bulk_s2g(void* dst, unsigned src, unsigned sz) {
    asm volatile("cp.async.bulk.global.shared::cta.bulk_group [%0], [%1], %2;"
                 :: "l"(dst), "r"(src), "r"(sz) : "memory");
}
__device__ __forceinline__ void bulk_commit() { asm volatile("cp.async.bulk.commit_group;" ::: "memory"); }
__device__ __forceinline__ void bulk_wait1() { asm volatile("cp.async.bulk.wait_group 1;" ::: "memory"); }
__device__ __forceinline__ void bulk_wait0() { asm volatile("cp.async.bulk.wait_group 0;" ::: "memory"); }
__device__ __forceinline__ void fence_async() { asm volatile("fence.proxy.async.shared::cta;" ::: "memory"); }

// rotated-quarter 64B row LDS/STS
__device__ __forceinline__ void lds_row(unsigned sbase, int lr, u64 (&x)[8]) {
#pragma unroll
    for (int i = 0; i < 4; i++) {
        int q = (i + lr) & 3; u64 a, b;
        asm volatile("ld.shared.v2.b64 {%0,%1},[%2];" : "=l"(a), "=l"(b) : "r"(sbase + lr * 64 + q * 16));
        x[2 * q] = a; x[2 * q + 1] = b;
    }
}
__device__ __forceinline__ void sts_row(unsigned sbase, int lr, const u64 (&x)[8]) {
#pragma unroll
    for (int i = 0; i < 4; i++) {
        int q = (i + lr) & 3;
        asm volatile("st.shared.v2.b64 [%0],{%1,%2};" :: "r"(sbase + lr * 64 + q * 16),
                     "l"(x[2 * q]), "l"(x[2 * q + 1]) : "memory");
    }
}

__device__ __forceinline__ void redu17(float (&acc)[17], float* __restrict__ dst) {
#pragma unroll
    for (int k = 0; k < 17; k++)
#pragma unroll
        for (int o = 16; o > 0; o >>= 1) acc[k] += __shfl_down_sync(0xffffffffu, acc[k], o);
    __shared__ float red[4][17];
    int lane = threadIdx.x & 31, wid = threadIdx.x >> 5;
    if (lane == 0) {
#pragma unroll
        for (int k = 0; k < 17; k++) red[wid][k] = acc[k];
    }
    __syncthreads();
    if (threadIdx.x < 17) {
        float s = 0.f;
#pragma unroll
        for (int w = 0; w < 4; w++) s += red[w][threadIdx.x];
        dst[threadIdx.x] = s;
    }
}

// glimpse finalize (last block); scratch overlaid on dead input smem
struct FinGS { float tA[7][17]; float tB[7][17]; float sA[17]; float sB[17]; float cat[48]; float sGW[768]; };
__device__ void fin_g(int t, char* scr, int bj, int nbm, const float* __restrict__ q0,
                      const float* __restrict__ gW, const float* __restrict__ gb,
                      float* __restrict__ dst, int* cnt) {
    FinGS* S = (FinGS*)scr;
    int col = t % 17, grp = t / 17;
    __syncthreads();
    if (grp < 7) {
        float a = 0.f, b = 0.f;
        for (int i = grp; i < bj;  i += 7) a += g_pJ[i * 17 + col];
        for (int i = grp; i < nbm; i += 7) b += g_pM[i * 17 + col];
        S->tA[grp][col] = a; S->tB[grp][col] = b;
    }
    for (int i = t; i < 768; i += BLOCK) S->sGW[i] = gW[i];
    __syncthreads();
    if (t < 17) {
        float a = 0.f, b = 0.f;
#pragma unroll
        for (int g = 0; g < 7; g++) { a += S->tA[g][t]; b += S->tB[g][t]; }
        S->sA[t] = a; S->sB[t] = b;
    }
    __syncthreads();
    if (t < 16) {
        S->cat[t] = q0[t];
        S->cat[16 + t] = S->sA[1 + t] / S->sA[0];
        S->cat[32 + t] = S->sB[1 + t] / S->sB[0];
    }
    __syncthreads();
    if (t < 16) {
        float g = gb[t];
#pragma unroll
        for (int d = 0; d < 48; d++) g += S->cat[d] * S->sGW[t * 48 + d];
        dst[t] = tanhf(g);
    }
    if (t == 0) *cnt = 0;
}

__device__ void fin_arg(int t, int which, float* __restrict__ out, int* cnt) {
    float bv = -3e38f, s = 0.f; int bi = IMAXX;
    for (int i = t; i < NBA; i += BLOCK) {
        float v = g_aV[i]; int ix = g_aI[i];
        if (v > bv || (v == bv && ix < bi)) { bv = v; bi = ix; }
        s += g_aS[i];
    }
#pragma unroll
    for (int o = 16; o > 0; o >>= 1) {
        float ov = __shfl_down_sync(0xffffffffu, bv, o);
        int   oi = __shfl_down_sync(0xffffffffu, bi, o);
        s += __shfl_down_sync(0xffffffffu, s, o);
        if (ov > bv || (ov == bv && oi < bi)) { bv = ov; bi = oi; }
    }
    __shared__ float wv[4], ws[4]; __shared__ int wi[4]; __shared__ int ssel;
    int lane = t & 31, wid = t >> 5;
    if (lane == 0) { wv[wid] = bv; wi[wid] = bi; ws[wid] = s; }
    __syncthreads();
    if (t == 0) {
        float v = wv[0]; int ix = wi[0]; float ss = ws[0];
#pragma unroll
        for (int w = 1; w < 4; w++) {
            if (wv[w] > v || (wv[w] == v && wi[w] < ix)) { v = wv[w]; ix = wi[w]; }
            ss += ws[w];
        }
        if (ix == IMAXX) ix = 0;
        if (which == 0) { g_selj = ix; g_logpj = v - logf(ss); ssel = ix; }
        else { out[0] = (float)g_selj; out[1] = (float)ix; out[2] = g_logpj + (v - logf(ss)); }
        *cnt = 0;
    }
    __syncthreads();
    if (which == 0 && t < 16) g_ejs[t] = g_Ej[ssel * 16 + t];
}

// ================= pass 1: embed + glimpse-1 (work-stealing, 2-in/2-out, 6 CTA/SM) =================
#define CHE 128
#define CBE (CHE * 64)
__global__ void __launch_bounds__(BLOCK, 6) k_emb(
    const float* __restrict__ jobs, const float* __restrict__ machs, int Nj, int Nm,
    const float* __restrict__ jW1, const float* __restrict__ jb1,
    const float* __restrict__ jW2, const float* __restrict__ jb2,
    const float* __restrict__ mW1, const float* __restrict__ mb1,
    const float* __restrict__ mW2, const float* __restrict__ mb2,
    const float* __restrict__ ajWr, const float* __restrict__ ajV,
    const float* __restrict__ ajWq, const float* __restrict__ ajbq,
    const float* __restrict__ amWr, const float* __restrict__ amV,
    const float* __restrict__ amWq, const float* __restrict__ ambq,
    const float* __restrict__ lastj, const float* __restrict__ g1W, const float* __restrict__ g1b)
{
    __shared__ __align__(128) char inb[2][CBE];
    __shared__ __align__(128) char outb[2][CBE];
    __shared__ u64 mbs[2];
    __shared__ int sq[2];
    __shared__ ulonglong2 sW1[64], sW2[64], sWr[64];
    __shared__ float sb1[16], sb2[16], sV[16], sQ[16];

    int t = threadIdx.x;
    int side = blockIdx.x >= BJE;
    int lb = side ? blockIdx.x - BJE : blockIdx.x;
    const float* X = side ? machs : jobs;
    int N = side ? Nm : Nj;
    float* Eo = side ? g_Em : g_Ej;
    float* part = (side ? g_pM : g_pJ) + lb * 17;
    int* sctr = side ? &g_s1 : &g_s0;
    const float* W1 = side ? mW1 : jW1; const float* b1 = side ? mb1 : jb1;
    const float* W2 = side ? mW2 : jW2; const float* b2 = side ? mb2 : jb2;
    const float* Wr = side ? amWr : ajWr; const float* V = side ? amV : ajV;
    const float* Wq = side ? amWq : ajWq; const float* bq = side ? ambq : ajbq;

    if (t < 64) {
        sW1[t] = ((const ulonglong2*)W1)[t];
        sW2[t] = ((const ulonglong2*)W2)[t];
        sWr[t] = ((const ulonglong2*)Wr)[t];
    }
    if (t < 16) {
        sb1[t] = b1[t]; sb2[t] = b2[t]; sV[t] = V[t];
        float q = bq[t];
#pragma unroll
        for (int d = 0; d < 16; d++) q += lastj[d] * Wq[t * 16 + d];
        sQ[t] = q;
    }
    if (t == 0) { mb_init(s2u(&mbs[0]), 1); mb_init(s2u(&mbs[1]), 1); }
    __syncthreads();

    int nch = (N + CHE - 1) / CHE;
    if (t == 0) {
#pragma unroll
        for (int s = 0; s < 2; s++) {
            int c = atomicAdd(sctr, 1);
            sq[s] = (c < nch) ? c : IMAXX;
            if (c < nch) {
                int rows = N - c * CHE; if (rows > CHE) rows = CHE;
                mb_tx(s2u(&mbs[s]), rows * 64);
                bulk_g2s(s2u(&inb[s][0]), (const void*)(X + (size_t)c * CHE * 16), rows * 64, s2u(&mbs[s]));
            }
        }
    }
    __syncthreads();

    float S = 0.f; u64 Wa[8];
#pragma unroll
    for (int k = 0; k < 8; k++) Wa[k] = 0ull;

    for (int k = 0; ; k++) {
        int s = k & 1;
        int c = sq[s];
        if (c == IMAXX) break;
        unsigned ph = (unsigned)((k >> 1) & 1);
        mb_wait(s2u(&mbs[s]), ph);

        int row0 = c * CHE;
        int rows = N - row0; if (rows > CHE) rows = CHE;
        bool ok = t < rows;
        u64 x[8], y[8];
        if (ok) lds_row(s2u(&inb[s][0]), t, x);
        else { for (int i = 0; i < 8; i++) x[i] = 0ull; }

        {   // layer 1
            float tp = 0.f;
#pragma unroll
            for (int j = 0; j < 16; j++) {
                u64 a = 0ull;
#pragma unroll
                for (int dd = 0; dd < 4; dd++) { ulonglong2 w = sW1[j * 4 + dd]; a = F2(x[2 * dd], w.x, a); a = F2(x[2 * dd + 1], w.y, a); }
                float2 u = unpack2(a); float tt = ftanh(u.x + u.y + sb1[j]);
                if (j & 1) y[j >> 1] = pack2(tp, tt); else tp = tt;
            }
        }
        {   // layer 2 -> embedding
            float tp = 0.f;
#pragma unroll
            for (int j = 0; j < 16; j++) {
                u64 a = 0ull;
#pragma unroll
                for (int dd = 0; dd < 4; dd++) { ulonglong2 w = sW2[j * 4 + dd]; a = F2(y[2 * dd], w.x, a); a = F2(y[2 * dd + 1], w.y, a); }
                float2 u = unpack2(a); float tt = ftanh(u.x + u.y + sb2[j]);
                if (j & 1) x[j >> 1] = pack2(tp, tt); else tp = tt;
            }
        }
        int os = k & 1;
        if (k >= 2 && t == 0) bulk_wait1();
        __syncthreads();
        if (ok) sts_row(s2u(&outb[os][0]), t, x);
        fence_async();
        if (ok) {   // glimpse-1 (split logit chains)
            float l0 = 0.f, l1 = 0.f;
#pragma unroll
            for (int j = 0; j < 16; j++) {
                u64 a = 0ull;
#pragma unroll
                for (int dd = 0; dd < 4; dd++) { ulonglong2 w = sWr[j * 4 + dd]; a = F2(x[2 * dd], w.x, a); a = F2(x[2 * dd + 1], w.y, a); }
                float2 u = unpack2(a); float v = sV[j] * ftanh(u.x + u.y + sQ[j]);
                if (j & 1) l1 += v; else l0 += v;
            }
            float w = __expf(l0 + l1); S += w;
            u64 wp = pack2(w, w);
#pragma unroll
            for (int kk = 0; kk < 8; kk++) Wa[kk] = F2(wp, x[kk], Wa[kk]);
        }
        __syncthreads();
        if (t == 0) {
            bulk_s2g((void*)(Eo + (size_t)row0 * 16), s2u(&outb[os][0]), rows * 64);
            bulk_commit();
            int cn = atomicAdd(sctr, 1);
            sq[s] = (cn < nch) ? cn : IMAXX;
            if (cn < nch) {
                int rn = N - cn * CHE; if (rn > CHE) rn = CHE;
                mb_tx(s2u(&mbs[s]), rn * 64);
                bulk_g2s(s2u(&inb[s][0]), (const void*)(X + (size_t)cn * CHE * 16), rn * 64, s2u(&mbs[s]));
            }
        }
    }
    if (t == 0) bulk_wait0();

    float acc[17]; acc[0] = S;
#pragma unroll
    for (int k = 0; k < 8; k++) { float2 u = unpack2(Wa[k]); acc[1 + 2 * k] = u.x; acc[2 + 2 * k] = u.y; }
    redu17(acc, part);
    __syncthreads();
    __shared__ int lastb;
    if (t == 0) { __threadfence(); lastb = (atomicAdd(&g_c0, 1) == NBE - 1); }
    __syncthreads();
    if (lastb) {
        fin_g(t, &inb[0][0], BJE, NBME, lastj, g1W, g1b, g_g1, &g_c0);
        if (t == 0) { g_s0 = 0; g_s1 = 0; }
    }
}

// ================= pass 3: glimpse-2 (work-stealing, 3-stage, 8 CTA/SM) =================
#define CHR 128
#define CBR (CHR * 64)
__global__ void __launch_bounds__(BLOCK, 8) k_gl(
    int Nj, int Nm,
    const float* __restrict__ ajWr, const float* __restrict__ ajV,
    const float* __restrict__ ajWq, const float* __restrict__ ajbq,
    const float* __restrict__ amWr, const float* __restrict__ amV,
    const float* __restrict__ amWq, const float* __restrict__ ambq,
    const float* __restrict__ g2W, const float* __restrict__ g2b)
{
    __shared__ __align__(128) char inb[3][CBR];
    __shared__ u64 mbs[3];
    __shared__ int sq[3];
    __shared__ ulonglong2 sWr[64];
    __shared__ float sV[16], sQ[16];

    int t = threadIdx.x;
    int side = blockIdx.x >= BJA;
    int lb = side ? blockIdx.x - BJA : blockIdx.x;
    const float* X = side ? g_Em : g_Ej;
    int N = side ? Nm : Nj;
    float* part = (side ? g_pM : g_pJ) + lb * 17;
    int* sctr = side ? &g_s4 : &g_s3;
    const float* Wr = side ? amWr : ajWr; const float* V = side ? amV : ajV;
    const float* Wq = side ? amWq : ajWq; const float* bq = side ? ambq : ajbq;

    if (t < 64) sWr[t] = ((const ulonglong2*)Wr)[t];
    if (t < 16) {
        sV[t] = V[t];
        float q = bq[t];
#pragma unroll
        for (int d = 0; d < 16; d++) q += g_ejs[d] * Wq[t * 16 + d];
        sQ[t] = q;
    }
    if (t == 0) {
#pragma unroll
        for (int s = 0; s < 3; s++) mb_init(s2u(&mbs[s]), 1);
    }
    __syncthreads();

    int nch = (N + CHR - 1) / CHR;
    if (t == 0) {
#pragma unroll
        for (int s = 0; s < 3; s++) {
            int c = atomicAdd(sctr, 1);
            sq[s] = (c < nch) ? c : IMAXX;
            if (c < nch) {
                int rows = N - c * CHR; if (rows > CHR) rows = CHR;
                mb_tx(s2u(&mbs[s]), rows * 64);
                bulk_g2s(s2u(&inb[s][0]), (const void*)(X + (size_t)c * CHR * 16), rows * 64, s2u(&mbs[s]));
            }
        }
    }
    __syncthreads();

    float S = 0.f; u64 Wa[8];
#pragma unroll
    for (int k = 0; k < 8; k++) Wa[k] = 0ull;

    for (int k = 0; ; k++) {
        int s = k % 3;
        int c = sq[s];
        if (c == IMAXX) break;
        unsigned ph = (unsigned)((k / 3) & 1);
        mb_wait(s2u(&mbs[s]), ph);

        int row0 = c * CHR;
        int rows = N - row0; if (rows > CHR) rows = CHR;
        if (t < rows) {
            u64 x[8];
            lds_row(s2u(&inb[s][0]), t, x);
            float l0 = 0.f, l1 = 0.f;
#pragma unroll
            for (int j = 0; j < 16; j++) {
                u64 a = 0ull;
#pragma unroll
                for (int dd = 0; dd < 4; dd++) { ulonglong2 w = sWr[j * 4 + dd]; a = F2(x[2 * dd], w.x, a); a = F2(x[2 * dd + 1], w.y, a); }
                float2 u = unpack2(a); float v = sV[j] * ftanh(u.x + u.y + sQ[j]);
                if (j & 1) l1 += v; else l0 += v;
            }
            float w = __expf(l0 + l1); S += w;
            u64 wp = pack2(w, w);
#pragma unroll
            for (int kk = 0; kk < 8; kk++) Wa[kk] = F2(wp, x[kk], Wa[kk]);
        }
        __syncthreads();
        if (t == 0) {
            int cn = atomicAdd(sctr, 1);
            sq[s] = (cn < nch) ? cn : IMAXX;
            if (cn < nch) {
                int rn = N - cn * CHR; if (rn > CHR) rn = CHR;
                mb_tx(s2u(&mbs[s]), rn * 64);
                bulk_g2s(s2u(&inb[s][0]), (const void*)(X + (size_t)cn * CHR * 16), rn * 64, s2u(&mbs[s]));
            }
        }
    }

    float acc[17]; acc[0] = S;
#pragma unroll
    for (int k = 0; k < 8; k++) { float2 u = unpack2(Wa[k]); acc[1 + 2 * k] = u.x; acc[2 + 2 * k] = u.y; }
    redu17(acc, part);
    __syncthreads();
    __shared__ int lastb;
    if (t == 0) { __threadfence(); lastb = (atomicAdd(&g_c2, 1) == NBA - 1); }
    __syncthreads();
    if (lastb) {
        fin_g(t, &inb[0][0], BJA, NBMA, g_ejs, g2W, g2b, g_g2, &g_c2);
        if (t == 0) { g_s3 = 0; g_s4 = 0; }
    }
}

// ================= passes 2 & 4: pointer logits (work-stealing, 3-stage, 8 CTA/SM) =================
__global__ void __launch_bounds__(BLOCK, 8) k_arg(
    int which, int N,
    const float* __restrict__ Wr, const float* __restrict__ V,
    const float* __restrict__ Wq, const float* __restrict__ bq,
    const void* __restrict__ maskp, int nmask, float* __restrict__ out)
{
    __shared__ __align__(128) char inb[3][CBR];
    __shared__ u64 mbs[3];
    __shared__ int sq[3];
    __shared__ ulonglong2 sWr[64];
    __shared__ float sV[16], sQ[16];
    __shared__ int smk;

    int t = threadIdx.x;
    const float* X = which ? g_Em : g_Ej;
    const float* qs = which ? g_g2 : g_g1;
    int* cnt = which ? &g_c3 : &g_c1;
    int* sctr = which ? &g_s5 : &g_s2;

    if (t == 0) smk = 0;
    if (t < 64) sWr[t] = ((const ulonglong2*)Wr)[t];
    if (t < 16) {
        sV[t] = V[t];
        float q = bq[t];
#pragma unroll
        for (int d = 0; d < 16; d++) q += qs[d] * Wq[t * 16 + d];
        sQ[t] = q;
    }
    if (t == 0) {
#pragma unroll
        for (int s = 0; s < 3; s++) mb_init(s2u(&mbs[s]), 1);
    }
    __syncthreads();
    // mask dtype detect: 0 = 4-byte elems, 1 = byte bools
    if (maskp) {
        int words = nmask >> 2; if (words > 4096) words = 4096;
        int f = 0;
        for (int i = t; i < words; i += BLOCK) {
            unsigned w = ((const unsigned*)maskp)[i];
            if (w != 0u && w != 1u && w != 0x3F800000u) f = 1;
        }
        if (f) atomicOr(&smk, 1);
    }
    __syncthreads();
    int mk = smk;

    int nch = (N + CHR - 1) / CHR;
    if (t == 0) {
#pragma unroll
        for (int s = 0; s < 3; s++) {
            int c = atomicAdd(sctr, 1);
            sq[s] = (c < nch) ? c : IMAXX;
            if (c < nch) {
                int rows = N - c * CHR; if (rows > CHR) rows = CHR;
                mb_tx(s2u(&mbs[s]), rows * 64);
                bulk_g2s(s2u(&inb[s][0]), (const void*)(X + (size_t)c * CHR * 16), rows * 64, s2u(&mbs[s]));
            }
        }
    }
    __syncthreads();

    float best = -3e38f, sum = 0.f; int bi = IMAXX;
    for (int k = 0; ; k++) {
        int s = k % 3;
        int c = sq[s];
        if (c == IMAXX) break;
        unsigned ph = (unsigned)((k / 3) & 1);
        mb_wait(s2u(&mbs[s]), ph);

        int row0 = c * CHR;
        int rows = N - row0; if (rows > CHR) rows = CHR;
        if (t < rows) {
            u64 x[8];
            lds_row(s2u(&inb[s][0]), t, x);
            float l0 = 0.f, l1 = 0.f;
#pragma unroll
            for (int j = 0; j < 16; j++) {
                u64 a = 0ull;
#pragma unroll
                for (int dd = 0; dd < 4; dd++) { ulonglong2 w = sWr[j * 4 + dd]; a = F2(x[2 * dd], w.x, a); a = F2(x[2 * dd + 1], w.y, a); }
                float2 u = unpack2(a); float v = sV[j] * ftanh(u.x + u.y + sQ[j]);
                if (j & 1) l1 += v; else l0 += v;
            }
            float l = l0 + l1;
            int row = row0 + t;
            bool pass = true;
            if (maskp) {
                if (mk) pass = ((const unsigned char*)maskp)[row] != 0;
                else    pass = ((const unsigned*)maskp)[row] != 0u;
            }
            if (pass) {
                sum += __expf(l);
                if (l > best) { best = l; bi = row; }
            }
        }
        __syncthreads();
        if (t == 0) {
            int cn = atomicAdd(sctr, 1);
            sq[s] = (cn < nch) ? cn : IMAXX;
            if (cn < nch) {
                int rn = N - cn * CHR; if (rn > CHR) rn = CHR;
                mb_tx(s2u(&mbs[s]), rn * 64);
                bulk_g2s(s2u(&inb[s][0]), (const void*)(X + (size_t)cn * CHR * 16), rn * 64, s2u(&mbs[s]));
            }
        }
    }
#pragma unroll
    for (int of = 16; of > 0; of >>= 1) {
        float ov = __shfl_down_sync(0xffffffffu, best, of);
        int   oi = __shfl_down_sync(0xffffffffu, bi, of);
        sum += __shfl_down_sync(0xffffffffu, sum, of);
        if (ov > best || (ov == best && oi < bi)) { best = ov; bi = oi; }
    }
    __shared__ float wv[4], ws[4]; __shared__ int wi[4];
    int lane = t & 31, wid = t >> 5;
    if (lane == 0) { wv[wid] = best; wi[wid] = bi; ws[wid] = sum; }
    __syncthreads();
    if (t == 0) {
        float v = wv[0]; int ix = wi[0]; float s = ws[0];
#pragma unroll
        for (int w = 1; w < 4; w++) {
            if (wv[w] > v || (wv[w] == v && wi[w] < ix)) { v = wv[w]; ix = wi[w]; }
            s += ws[w];
        }
        g_aV[blockIdx.x] = v; g_aI[blockIdx.x] = ix; g_aS[blockIdx.x] = s;
    }
    __syncthreads();
    __shared__ int lastb;
    if (t == 0) { __threadfence(); lastb = (atomicAdd(cnt, 1) == NBA - 1); }
    __syncthreads();
    if (lastb) {
        fin_arg(t, which, out, cnt);
        if (t == 0) { if (which) g_s5 = 0; else g_s2 = 0; }
    }
}

extern "C" void kernel_launch(void* const* d_in, const int* in_sizes, int n_in,
                              void* d_out, int out_size) {
    const float* jobs  = (const float*)d_in[0];
    const float* machs = (const float*)d_in[1];
    const void*  mask  = d_in[2];
    const float *jW1=(const float*)d_in[3], *jb1=(const float*)d_in[4], *jW2=(const float*)d_in[5], *jb2=(const float*)d_in[6];
    const float *mW1=(const float*)d_in[7], *mb1=(const float*)d_in[8], *mW2=(const float*)d_in[9], *mb2=(const float*)d_in[10];
    const float *ajWq=(const float*)d_in[11], *ajbq=(const float*)d_in[12], *ajWr=(const float*)d_in[13], *ajV=(const float*)d_in[14];
    const float *amWq=(const float*)d_in[15], *ambq=(const float*)d_in[16], *amWr=(const float*)d_in[17], *amV=(const float*)d_in[18];
    const float *jaWq=(const float*)d_in[19], *jabq=(const float*)d_in[20], *jaWr=(const float*)d_in[21], *jaV=(const float*)d_in[22];
    const float *maWq=(const float*)d_in[23], *mabq=(const float*)d_in[24], *maWr=(const float*)d_in[25], *maV=(const float*)d_in[26];
    const float *g1W=(const float*)d_in[27], *g1b=(const float*)d_in[28];
    const float *g2W=(const float*)d_in[29], *g2b=(const float*)d_in[30];
    const float *lastj=(const float*)d_in[31];
    int Nj = in_sizes[0] / 16;
    int Nm = in_sizes[1] / 16;
    float* out = (float*)d_out;

    k_emb<<<NBE, BLOCK>>>(jobs, machs, Nj, Nm, jW1, jb1, jW2, jb2, mW1, mb1, mW2, mb2,
                          ajWr, ajV, ajWq, ajbq, amWr, amV, amWq, ambq, lastj, g1W, g1b);
    k_arg<<<NBA, BLOCK>>>(0, Nj, jaWr, jaV, jaWq, jabq, mask, in_sizes[2], out);
    k_gl <<<NBA, BLOCK>>>(Nj, Nm, ajWr, ajV, ajWq, ajbq, amWr, amV, amWq, ambq, g2W, g2b);
    k_arg<<<NBA, BLOCK>>>(1, Nm, maWr, maV, maWq, mabq, nullptr, 0, out);
    (void)n_in; (void)out_size;
}

// round 12
// speedup vs baseline: 1.0184x; 1.0184x over previous
#include <cuda_runtime.h>
#include <math.h>

#define BLOCK 128
#define NBG 888
#define BJG 592
#define NBMG (NBG - BJG)
#define IMAXX 0x7fffffff
typedef unsigned long long u64;

__device__ float g_Ej[16000000];
__device__ float g_Em[8000000];
__device__ float g_pJ[BJG * 17], g_pM[NBMG * 17];
__device__ float g_aV[NBG]; __device__ int g_aI[NBG]; __device__ float g_aS[NBG];
__device__ float g_g1[16], g_g2[16], g_ejs[16];
__device__ float g_logpj; __device__ int g_selj;
__device__ int g_c0, g_c1, g_c2, g_c3;
__device__ int g_s0, g_s1, g_s2, g_s3, g_s4, g_s5;

// ---------- packed f32x2 + fast math ----------
__device__ __forceinline__ u64 F2(u64 a, u64 b, u64 c) {
    u64 r; asm("fma.rn.f32x2 %0,%1,%2,%3;" : "=l"(r) : "l"(a), "l"(b), "l"(c)); return r;
}
__device__ __forceinline__ u64 pack2(float lo, float hi) {
    u64 r; asm("mov.b64 %0,{%1,%2};" : "=l"(r) : "f"(lo), "f"(hi)); return r;
}
__device__ __forceinline__ float2 unpack2(u64 v) {
    float2 r; asm("mov.b64 {%0,%1},%2;" : "=f"(r.x), "=f"(r.y) : "l"(v)); return r;
}
__device__ __forceinline__ float ftanh(float x) {
    float r; asm("tanh.approx.f32 %0,%1;" : "=f"(r) : "f"(x)); return r;
}

// ---------- L2 eviction policies ----------
__device__ __forceinline__ u64 pol_evict_last() {
    u64 p; asm("createpolicy.fractional.L2::evict_last.b64 %0, 1.0;" : "=l"(p)); return p;
}
__device__ __forceinline__ u64 pol_evict_first() {
    u64 p; asm("createpolicy.fractional.L2::evict_first.b64 %0, 1.0;" : "=l"(p)); return p;
}

// ---------- bulk-async + mbarrier ----------
__device__ __forceinline__ unsigned s2u(const void* p) { return (unsigned)__cvta_generic_to_shared(p); }
__device__ __forceinline__ void mb_init(unsigned a, unsigned c) {
    asm volatile("mbarrier.init.shared.b64 [%0], %1;" :: "r"(a), "r"(c) : "memory");
}
__device__ __forceinline__ void mb_tx(unsigned a, unsigned bytes) {
    asm volatile("mbarrier.arrive.expect_tx.shared.b64 _, [%0], %1;" :: "r"(a), "r"(bytes) : "memory");
}
__device__ __forceinline__ void mb_wait(unsigned a, unsigned p) {
    asm volatile(
        "{\n\t.reg .pred P;\n"
        "WL%=:\n\t"
        "mbarrier.try_wait.parity.acquire.cta.shared::cta.b64 P, [%0], %1, 0x989680;\n\t"
        "@P bra WD%=;\n\t"
        "bra WL%=;\n"
        "WD%=:\n\t}"
        :: "r"(a), "r"(p) : "memory");
}
__device__ __forceinline__ void bulk_g2s(unsigned dst, const void* src, unsigned sz, unsigned mb, u64 pol) {
    asm volatile("cp.async.bulk.shared::cluster.global.mbarrier::complete_tx::bytes.L2::cache_hint "
                 "[%0], [%1], %2, [%3], %4;"
                 :: "r"(dst), "l"(src), "r"(sz), "r"(mb), "l"(pol) : "memory");
}
__device__ __forceinline__ void bulk_s2g(void* dst, unsigned src, unsigned sz, u64 pol) {
    asm volatile("cp.async.bulk.global.shared::cta.bulk_group.L2::cache_hint [%0], [%1], %2, %3;"
                 :: "l"(dst), "r"(src), "r"(sz), "l"(pol) : "memory");
}
__device__ __forceinline__ void bulk_commit() { asm volatile("cp.async.bulk.commit_group;" ::: "memory"); }
__device__ __forceinline__ void bulk_wait1() { asm volatile("cp.async.bulk.wait_group 1;" ::: "memory"); }
__device__ __forceinline__ void bulk_wait0() { asm volatile("cp.async.bulk.wait_group 0;" ::: "memory"); }
__device__ __forceinline__ void fence_async() { asm volatile("fence.proxy.async.shared::cta;" ::: "memory"); }

// rotated-quarter 64B row LDS/STS
__device__ __forceinline__ void lds_row(unsigned sbase, int lr, u64 (&x)[8]) {
#pragma unroll
    for (int i = 0; i < 4; i++) {
        int q = (i + lr) & 3; u64 a, b;
        asm volatile("ld.shared.v2.b64 {%0,%1},[%2];" : "=l"(a), "=l"(b) : "r"(sbase + lr * 64 + q * 16));
        x[2 * q] = a; x[2 * q + 1] = b;
    }
}
__device__ __forceinline__ void sts_row(unsigned sbase, int lr, const u64 (&x)[8]) {
#pragma unroll
    for (int i = 0; i < 4; i++) {
        int q = (i + lr) & 3;
        asm volatile("st.shared.v2.b64 [%0],{%1,%2};" :: "r"(sbase + lr * 64 + q * 16),
                     "l"(x[2 * q]), "l"(x[2 * q + 1]) : "memory");
    }
}

__device__ __forceinline__ void redu17(float (&acc)[17], float* __restrict__ dst) {
#pragma unroll
    for (int k = 0; k < 17; k++)
#pragma unroll
        for (int o = 16; o > 0; o >>= 1) acc[k] += __shfl_down_sync(0xffffffffu, acc[k], o);
    __shared__ float red[4][17];
    int lane = threadIdx.x & 31, wid = threadIdx.x >> 5;
    if (lane == 0) {
#pragma unroll
        for (int k = 0; k < 17; k++) red[wid][k] = acc[k];
    }
    __syncthreads();
    if (threadIdx.x < 17) {
        float s = 0.f;
#pragma unroll
        for (int w = 0; w < 4; w++) s += red[w][threadIdx.x];
        dst[threadIdx.x] = s;
    }
}

// glimpse finalize (last block); scratch overlaid on dead input smem
struct FinGS { float tA[7][17]; float tB[7][17]; float sA[17]; float sB[17]; float cat[48]; float sGW[768]; };
__device__ void fin_g(int t, char* scr, const float* __restrict__ q0,
                      const float* __restrict__ gW, const float* __restrict__ gb,
                      float* __restrict__ dst, int* cnt) {
    FinGS* S = (FinGS*)scr;
    int col = t % 17, grp = t / 17;
    __syncthreads();
    if (grp < 7) {
        float a = 0.f, b = 0.f;
        for (int i = grp; i < BJG;  i += 7) a += g_pJ[i * 17 + col];
        for (int i = grp; i < NBMG; i += 7) b += g_pM[i * 17 + col];
        S->tA[grp][col] = a; S->tB[grp][col] = b;
    }
    for (int i = t; i < 768; i += BLOCK) S->sGW[i] = gW[i];
    __syncthreads();
    if (t < 17) {
        float a = 0.f, b = 0.f;
#pragma unroll
        for (int g = 0; g < 7; g++) { a += S->tA[g][t]; b += S->tB[g][t]; }
        S->sA[t] = a; S->sB[t] = b;
    }
    __syncthreads();
    if (t < 16) {
        S->cat[t] = q0[t];
        S->cat[16 + t] = S->sA[1 + t] / S->sA[0];
        S->cat[32 + t] = S->sB[1 + t] / S->sB[0];
    }
    __syncthreads();
    if (t < 16) {
        float g = gb[t];
#pragma unroll
        for (int d = 0; d < 48; d++) g += S->cat[d] * S->sGW[t * 48 + d];
        dst[t] = tanhf(g);
    }
    if (t == 0) *cnt = 0;
}

__device__ void fin_arg(int t, int which, float* __restrict__ out, int* cnt) {
    float bv = -3e38f, s = 0.f; int bi = IMAXX;
    for (int i = t; i < NBG; i += BLOCK) {
        float v = g_aV[i]; int ix = g_aI[i];
        if (v > bv || (v == bv && ix < bi)) { bv = v; bi = ix; }
        s += g_aS[i];
    }
#pragma unroll
    for (int o = 16; o > 0; o >>= 1) {
        float ov = __shfl_down_sync(0xffffffffu, bv, o);
        int   oi = __shfl_down_sync(0xffffffffu, bi, o);
        s += __shfl_down_sync(0xffffffffu, s, o);
        if (ov > bv || (ov == bv && oi < bi)) { bv = ov; bi = oi; }
    }
    __shared__ float wv[4], ws[4]; __shared__ int wi[4]; __shared__ int ssel;
    int lane = t & 31, wid = t >> 5;
    if (lane == 0) { wv[wid] = bv; wi[wid] = bi; ws[wid] = s; }
    __syncthreads();
    if (t == 0) {
        float v = wv[0]; int ix = wi[0]; float ss = ws[0];
#pragma unroll
        for (int w = 1; w < 4; w++) {
            if (wv[w] > v || (wv[w] == v && wi[w] < ix)) { v = wv[w]; ix = wi[w]; }
            ss += ws[w];
        }
        if (ix == IMAXX) ix = 0;
        if (which == 0) { g_selj = ix; g_logpj = v - logf(ss); ssel = ix; }
        else { out[0] = (float)g_selj; out[1] = (float)ix; out[2] = g_logpj + (v - logf(ss)); }
        *cnt = 0;
    }
    __syncthreads();
    if (which == 0 && t < 16) g_ejs[t] = g_Ej[ssel * 16 + t];
}

// ================= pass 1: embed + glimpse-1 (work-stealing, 2-in/2-out) =================
#define CHE 128
#define CBE (CHE * 64)
__global__ void __launch_bounds__(BLOCK, 6) k_emb(
    const float* __restrict__ jobs, const float* __restrict__ machs, int Nj, int Nm,
    const float* __restrict__ jW1, const float* __restrict__ jb1,
    const float* __restrict__ jW2, const float* __restrict__ jb2,
    const float* __restrict__ mW1, const float* __restrict__ mb1,
    const float* __restrict__ mW2, const float* __restrict__ mb2,
    const float* __restrict__ ajWr, const float* __restrict__ ajV,
    const float* __restrict__ ajWq, const float* __restrict__ ajbq,
    const float* __restrict__ amWr, const float* __restrict__ amV,
    const float* __restrict__ amWq, const float* __restrict__ ambq,
    const float* __restrict__ lastj, const float* __restrict__ g1W, const float* __restrict__ g1b)
{
    __shared__ __align__(128) char inb[2][CBE];
    __shared__ __align__(128) char outb[2][CBE];
    __shared__ u64 mbs[2];
    __shared__ int sq[2];
    __shared__ ulonglong2 sW1[64], sW2[64], sWr[64];
    __shared__ float sb1[16], sb2[16], sV[16], sQ[16];

    int t = threadIdx.x;
    int side = blockIdx.x >= BJG;
    int lb = side ? blockIdx.x - BJG : blockIdx.x;
    const float* X = side ? machs : jobs;
    int N = side ? Nm : Nj;
    float* Eo = side ? g_Em : g_Ej;
    float* part = (side ? g_pM : g_pJ) + lb * 17;
    int* sctr = side ? &g_s1 : &g_s0;
    const float* W1 = side ? mW1 : jW1; const float* b1 = side ? mb1 : jb1;
    const float* W2 = side ? mW2 : jW2; const float* b2 = side ? mb2 : jb2;
    const float* Wr = side ? amWr : ajWr; const float* V = side ? amV : ajV;
    const float* Wq = side ? amWq : ajWq; const float* bq = side ? ambq : ajbq;

    u64 pfirst = pol_evict_first();   // raw inputs: stream, don't pollute L2
    u64 plast  = pol_evict_last();    // E: keep resident for later passes

    if (t < 64) {
        sW1[t] = ((const ulonglong2*)W1)[t];
        sW2[t] = ((const ulonglong2*)W2)[t];
        sWr[t] = ((const ulonglong2*)Wr)[t];
    }
    if (t < 16) {
        sb1[t] = b1[t]; sb2[t] = b2[t]; sV[t] = V[t];
        float q = bq[t];
#pragma unroll
        for (int d = 0; d < 16; d++) q += lastj[d] * Wq[t * 16 + d];
        sQ[t] = q;
    }
    if (t == 0) { mb_init(s2u(&mbs[0]), 1); mb_init(s2u(&mbs[1]), 1); }
    __syncthreads();

    int nch = (N + CHE - 1) / CHE;
    if (t == 0) {
#pragma unroll
        for (int s = 0; s < 2; s++) {
            int c = atomicAdd(sctr, 1);
            sq[s] = (c < nch) ? c : IMAXX;
            if (c < nch) {
                int rows = N - c * CHE; if (rows > CHE) rows = CHE;
                mb_tx(s2u(&mbs[s]), rows * 64);
                bulk_g2s(s2u(&inb[s][0]), (const void*)(X + (size_t)c * CHE * 16), rows * 64, s2u(&mbs[s]), pfirst);
            }
        }
    }
    __syncthreads();

    float S = 0.f; u64 Wa[8];
#pragma unroll
    for (int k = 0; k < 8; k++) Wa[k] = 0ull;

    for (int k = 0; ; k++) {
        int s = k & 1;
        int c = sq[s];
        if (c == IMAXX) break;
        unsigned ph = (unsigned)((k >> 1) & 1);
        mb_wait(s2u(&mbs[s]), ph);

        int row0 = c * CHE;
        int rows = N - row0; if (rows > CHE) rows = CHE;
        bool ok = t < rows;
        u64 x[8], y[8];
        if (ok) lds_row(s2u(&inb[s][0]), t, x);
        else { for (int i = 0; i < 8; i++) x[i] = 0ull; }

        {   // layer 1
            float tp = 0.f;
#pragma unroll
            for (int j = 0; j < 16; j++) {
                u64 a = 0ull;
#pragma unroll
                for (int dd = 0; dd < 4; dd++) { ulonglong2 w = sW1[j * 4 + dd]; a = F2(x[2 * dd], w.x, a); a = F2(x[2 * dd + 1], w.y, a); }
                float2 u = unpack2(a); float tt = ftanh(u.x + u.y + sb1[j]);
                if (j & 1) y[j >> 1] = pack2(tp, tt); else tp = tt;
            }
        }
        {   // layer 2 -> embedding
            float tp = 0.f;
#pragma unroll
            for (int j = 0; j < 16; j++) {
                u64 a = 0ull;
#pragma unroll
                for (int dd = 0; dd < 4; dd++) { ulonglong2 w = sW2[j * 4 + dd]; a = F2(y[2 * dd], w.x, a); a = F2(y[2 * dd + 1], w.y, a); }
                float2 u = unpack2(a); float tt = ftanh(u.x + u.y + sb2[j]);
                if (j & 1) x[j >> 1] = pack2(tp, tt); else tp = tt;
            }
        }
        int os = k & 1;
        if (k >= 2 && t == 0) bulk_wait1();
        __syncthreads();
        if (ok) sts_row(s2u(&outb[os][0]), t, x);
        fence_async();
        if (ok) {   // glimpse-1 (split logit chains)
            float l0 = 0.f, l1 = 0.f;
#pragma unroll
            for (int j = 0; j < 16; j++) {
                u64 a = 0ull;
#pragma unroll
                for (int dd = 0; dd < 4; dd++) { ulonglong2 w = sWr[j * 4 + dd]; a = F2(x[2 * dd], w.x, a); a = F2(x[2 * dd + 1], w.y, a); }
                float2 u = unpack2(a); float v = sV[j] * ftanh(u.x + u.y + sQ[j]);
                if (j & 1) l1 += v; else l0 += v;
            }
            float w = __expf(l0 + l1); S += w;
            u64 wp = pack2(w, w);
#pragma unroll
            for (int kk = 0; kk < 8; kk++) Wa[kk] = F2(wp, x[kk], Wa[kk]);
        }
        __syncthreads();
        if (t == 0) {
            bulk_s2g((void*)(Eo + (size_t)row0 * 16), s2u(&outb[os][0]), rows * 64, plast);
            bulk_commit();
            int cn = atomicAdd(sctr, 1);
            sq[s] = (cn < nch) ? cn : IMAXX;
            if (cn < nch) {
                int rn = N - cn * CHE; if (rn > CHE) rn = CHE;
                mb_tx(s2u(&mbs[s]), rn * 64);
                bulk_g2s(s2u(&inb[s][0]), (const void*)(X + (size_t)cn * CHE * 16), rn * 64, s2u(&mbs[s]), pfirst);
            }
        }
    }
    if (t == 0) bulk_wait0();

    float acc[17]; acc[0] = S;
#pragma unroll
    for (int k = 0; k < 8; k++) { float2 u = unpack2(Wa[k]); acc[1 + 2 * k] = u.x; acc[2 + 2 * k] = u.y; }
    redu17(acc, part);
    __syncthreads();
    __shared__ int lastb;
    if (t == 0) { __threadfence(); lastb = (atomicAdd(&g_c0, 1) == NBG - 1); }
    __syncthreads();
    if (lastb) {
        fin_g(t, &inb[0][0], lastj, g1W, g1b, g_g1, &g_c0);
        if (t == 0) { g_s0 = 0; g_s1 = 0; }
    }
}

// ================= pass 3: glimpse-2 (work-stealing, 4-stage, 1 row/thread) =================
#define CHR 128
#define CBR (CHR * 64)
__global__ void __launch_bounds__(BLOCK, 6) k_gl(
    int Nj, int Nm,
    const float* __restrict__ ajWr, const float* __restrict__ ajV,
    const float* __restrict__ ajWq, const float* __restrict__ ajbq,
    const float* __restrict__ amWr, const float* __restrict__ amV,
    const float* __restrict__ amWq, const float* __restrict__ ambq,
    const float* __restrict__ g2W, const float* __restrict__ g2b)
{
    __shared__ __align__(128) char inb[4][CBR];
    __shared__ u64 mbs[4];
    __shared__ int sq[4];
    __shared__ ulonglong2 sWr[64];
    __shared__ float sV[16], sQ[16];

    int t = threadIdx.x;
    int side = blockIdx.x >= BJG;
    int lb = side ? blockIdx.x - BJG : blockIdx.x;
    const float* X = side ? g_Em : g_Ej;
    int N = side ? Nm : Nj;
    float* part = (side ? g_pM : g_pJ) + lb * 17;
    int* sctr = side ? &g_s4 : &g_s3;
    const float* Wr = side ? amWr : ajWr; const float* V = side ? amV : ajV;
    const float* Wq = side ? amWq : ajWq; const float* bq = side ? ambq : ajbq;

    u64 plast = pol_evict_last();

    if (t < 64) sWr[t] = ((const ulonglong2*)Wr)[t];
    if (t < 16) {
        sV[t] = V[t];
        float q = bq[t];
#pragma unroll
        for (int d = 0; d < 16; d++) q += g_ejs[d] * Wq[t * 16 + d];
        sQ[t] = q;
    }
    if (t == 0) {
#pragma unroll
        for (int s = 0; s < 4; s++) mb_init(s2u(&mbs[s]), 1);
    }
    __syncthreads();

    int nch = (N + CHR - 1) / CHR;
    if (t == 0) {
#pragma unroll
        for (int s = 0; s < 4; s++) {
            int c = atomicAdd(sctr, 1);
            sq[s] = (c < nch) ? c : IMAXX;
            if (c < nch) {
                int rows = N - c * CHR; if (rows > CHR) rows = CHR;
                mb_tx(s2u(&mbs[s]), rows * 64);
                bulk_g2s(s2u(&inb[s][0]), (const void*)(X + (size_t)c * CHR * 16), rows * 64, s2u(&mbs[s]), plast);
            }
        }
    }
    __syncthreads();

    float S = 0.f; u64 Wa[8];
#pragma unroll
    for (int k = 0; k < 8; k++) Wa[k] = 0ull;

    for (int k = 0; ; k++) {
        int s = k & 3;
        int c = sq[s];
        if (c == IMAXX) break;
        unsigned ph = (unsigned)((k >> 2) & 1);
        mb_wait(s2u(&mbs[s]), ph);

        int row0 = c * CHR;
        int rows = N - row0; if (rows > CHR) rows = CHR;
        if (t < rows) {
            u64 x[8];
            lds_row(s2u(&inb[s][0]), t, x);
            float l0 = 0.f, l1 = 0.f;
#pragma unroll
            for (int j = 0; j < 16; j++) {
                u64 a = 0ull;
#pragma unroll
                for (int dd = 0; dd < 4; dd++) { ulonglong2 w = sWr[j * 4 + dd]; a = F2(x[2 * dd], w.x, a); a = F2(x[2 * dd + 1], w.y, a); }
                float2 u = unpack2(a); float v = sV[j] * ftanh(u.x + u.y + sQ[j]);
                if (j & 1) l1 += v; else l0 += v;
            }
            float w = __expf(l0 + l1); S += w;
            u64 wp = pack2(w, w);
#pragma unroll
            for (int kk = 0; kk < 8; kk++) Wa[kk] = F2(wp, x[kk], Wa[kk]);
        }
        __syncthreads();
        if (t == 0) {
            int cn = atomicAdd(sctr, 1);
            sq[s] = (cn < nch) ? cn : IMAXX;
            if (cn < nch) {
                int rn = N - cn * CHR; if (rn > CHR) rn = CHR;
                mb_tx(s2u(&mbs[s]), rn * 64);
                bulk_g2s(s2u(&inb[s][0]), (const void*)(X + (size_t)cn * CHR * 16), rn * 64, s2u(&mbs[s]), plast);
            }
        }
    }

    float acc[17]; acc[0] = S;
#pragma unroll
    for (int k = 0; k < 8; k++) { float2 u = unpack2(Wa[k]); acc[1 + 2 * k] = u.x; acc[2 + 2 * k] = u.y; }
    redu17(acc, part);
    __syncthreads();
    __shared__ int lastb;
    if (t == 0) { __threadfence(); lastb = (atomicAdd(&g_c2, 1) == NBG - 1); }
    __syncthreads();
    if (lastb) {
        fin_g(t, &inb[0][0], g_ejs, g2W, g2b, g_g2, &g_c2);
        if (t == 0) { g_s3 = 0; g_s4 = 0; }
    }
}

// ================= passes 2 & 4: pointer logits (work-stealing, 4-stage) =================
__global__ void __launch_bounds__(BLOCK, 6) k_arg(
    int which, int N,
    const float* __restrict__ Wr, const float* __restrict__ V,
    const float* __restrict__ Wq, const float* __restrict__ bq,
    const void* __restrict__ maskp, int nmask, float* __restrict__ out)
{
    __shared__ __align__(128) char inb[4][CBR];
    __shared__ u64 mbs[4];
    __shared__ int sq[4];
    __shared__ ulonglong2 sWr[64];
    __shared__ float sV[16], sQ[16];
    __shared__ int smk;

    int t = threadIdx.x;
    const float* X = which ? g_Em : g_Ej;
    const float* qs = which ? g_g2 : g_g1;
    int* cnt = which ? &g_c3 : &g_c1;
    int* sctr = which ? &g_s5 : &g_s2;

    u64 plast = pol_evict_last();

    if (t == 0) smk = 0;
    if (t < 64) sWr[t] = ((const ulonglong2*)Wr)[t];
    if (t < 16) {
        sV[t] = V[t];
        float q = bq[t];
#pragma unroll
        for (int d = 0; d < 16; d++) q += qs[d] * Wq[t * 16 + d];
        sQ[t] = q;
    }
    if (t == 0) {
#pragma unroll
        for (int s = 0; s < 4; s++) mb_init(s2u(&mbs[s]), 1);
    }
    __syncthreads();
    // mask dtype detect: 0 = 4-byte elems, 1 = byte bools
    if (maskp) {
        int words = nmask >> 2; if (words > 4096) words = 4096;
        int f = 0;
        for (int i = t; i < words; i += BLOCK) {
            unsigned w = ((const unsigned*)maskp)[i];
            if (w != 0u && w != 1u && w != 0x3F800000u) f = 1;
        }
        if (f) atomicOr(&smk, 1);
    }
    __syncthreads();
    int mk = smk;

    int nch = (N + CHR - 1) / CHR;
    if (t == 0) {
#pragma unroll
        for (int s = 0; s < 4; s++) {
            int c = atomicAdd(sctr, 1);
            sq[s] = (c < nch) ? c : IMAXX;
            if (c < nch) {
                int rows = N - c * CHR; if (rows > CHR) rows = CHR;
                mb_tx(s2u(&mbs[s]), rows * 64);
                bulk_g2s(s2u(&inb[s][0]), (const void*)(X + (size_t)c * CHR * 16), rows * 64, s2u(&mbs[s]), plast);
            }
        }
    }
    __syncthreads();

    float best = -3e38f, sum = 0.f; int bi = IMAXX;
    for (int k = 0; ; k++) {
        int s = k & 3;
        int c = sq[s];
        if (c == IMAXX) break;
        unsigned ph = (unsigned)((k >> 2) & 1);
        mb_wait(s2u(&mbs[s]), ph);

        int row0 = c * CHR;
        int rows = N - row0; if (rows > CHR) rows = CHR;
        if (t < rows) {
            u64 x[8];
            lds_row(s2u(&inb[s][0]), t, x);
            float l0 = 0.f, l1 = 0.f;
#pragma unroll
            for (int j = 0; j < 16; j++) {
                u64 a = 0ull;
#pragma unroll
                for (int dd = 0; dd < 4; dd++) { ulonglong2 w = sWr[j * 4 + dd]; a = F2(x[2 * dd], w.x, a); a = F2(x[2 * dd + 1], w.y, a); }
                float2 u = unpack2(a); float v = sV[j] * ftanh(u.x + u.y + sQ[j]);
                if (j & 1) l1 += v; else l0 += v;
            }
            float l = l0 + l1;
            int row = row0 + t;
            bool pass = true;
            if (maskp) {
                if (mk) pass = ((const unsigned char*)maskp)[row] != 0;
                else    pass = ((const unsigned*)maskp)[row] != 0u;
            }
            if (pass) {
                sum += __expf(l);
                if (l > best) { best = l; bi = row; }
            }
        }
        __syncthreads();
        if (t == 0) {
            int cn = atomicAdd(sctr, 1);
            sq[s] = (cn < nch) ? cn : IMAXX;
            if (cn < nch) {
                int rn = N - cn * CHR; if (rn > CHR) rn = CHR;
                mb_tx(s2u(&mbs[s]), rn * 64);
                bulk_g2s(s2u(&inb[s][0]), (const void*)(X + (size_t)cn * CHR * 16), rn * 64, s2u(&mbs[s]), plast);
            }
        }
    }
#pragma unroll
    for (int of = 16; of > 0; of >>= 1) {
        float ov = __shfl_down_sync(0xffffffffu, best, of);
        int   oi = __shfl_down_sync(0xffffffffu, bi, of);
        sum += __shfl_down_sync(0xffffffffu, sum, of);
        if (ov > best || (ov == best && oi < bi)) { best = ov; bi = oi; }
    }
    __shared__ float wv[4], ws[4]; __shared__ int wi[4];
    int lane = t & 31, wid = t >> 5;
    if (lane == 0) { wv[wid] = best; wi[wid] = bi; ws[wid] = sum; }
    __syncthreads();
    if (t == 0) {
        float v = wv[0]; int ix = wi[0]; float s = ws[0];
#pragma unroll
        for (int w = 1; w < 4; w++) {
            if (wv[w] > v || (wv[w] == v && wi[w] < ix)) { v = wv[w]; ix = wi[w]; }
            s += ws[w];
        }
        g_aV[blockIdx.x] = v; g_aI[blockIdx.x] = ix; g_aS[blockIdx.x] = s;
    }
    __syncthreads();
    __shared__ int lastb;
    if (t == 0) { __threadfence(); lastb = (atomicAdd(cnt, 1) == NBG - 1); }
    __syncthreads();
    if (lastb) {
        fin_arg(t, which, out, cnt);
        if (t == 0) { if (which) g_s5 = 0; else g_s2 = 0; }
    }
}

extern "C" void kernel_launch(void* const* d_in, const int* in_sizes, int n_in,
                              void* d_out, int out_size) {
    const float* jobs  = (const float*)d_in[0];
    const float* machs = (const float*)d_in[1];
    const void*  mask  = d_in[2];
    const float *jW1=(const float*)d_in[3], *jb1=(const float*)d_in[4], *jW2=(const float*)d_in[5], *jb2=(const float*)d_in[6];
    const float *mW1=(const float*)d_in[7], *mb1=(const float*)d_in[8], *mW2=(const float*)d_in[9], *mb2=(const float*)d_in[10];
    const float *ajWq=(const float*)d_in[11], *ajbq=(const float*)d_in[12], *ajWr=(const float*)d_in[13], *ajV=(const float*)d_in[14];
    const float *amWq=(const float*)d_in[15], *ambq=(const float*)d_in[16], *amWr=(const float*)d_in[17], *amV=(const float*)d_in[18];
    const float *jaWq=(const float*)d_in[19], *jabq=(const float*)d_in[20], *jaWr=(const float*)d_in[21], *jaV=(const float*)d_in[22];
    const float *maWq=(const float*)d_in[23], *mabq=(const float*)d_in[24], *maWr=(const float*)d_in[25], *maV=(const float*)d_in[26];
    const float *g1W=(const float*)d_in[27], *g1b=(const float*)d_in[28];
    const float *g2W=(const float*)d_in[29], *g2b=(const float*)d_in[30];
    const float *lastj=(const float*)d_in[31];
    int Nj = in_sizes[0] / 16;
    int Nm = in_sizes[1] / 16;
    float* out = (float*)d_out;

    k_emb<<<NBG, BLOCK>>>(jobs, machs, Nj, Nm, jW1, jb1, jW2, jb2, mW1, mb1, mW2, mb2,
                          ajWr, ajV, ajWq, ajbq, amWr, amV, amWq, ambq, lastj, g1W, g1b);
    k_arg<<<NBG, BLOCK>>>(0, Nj, jaWr, jaV, jaWq, jabq, mask, in_sizes[2], out);
    k_gl <<<NBG, BLOCK>>>(Nj, Nm, ajWr, ajV, ajWq, ajbq, amWr, amV, amWq, ambq, g2W, g2b);
    k_arg<<<NBG, BLOCK>>>(1, Nm, maWr, maV, maWq, mabq, nullptr, 0, out);
    (void)n_in; (void)out_size;
}

// round 13
// speedup vs baseline: 1.3169x; 1.2931x over previous
#include <cuda_runtime.h>
#include <math.h>

#define BLOCK 128
#define NBG 888
#define BJG 592
#define NBMG (NBG - BJG)
#define IMAXX 0x7fffffff
typedef unsigned long long u64;
typedef unsigned short u16;

__device__ u16 g_Ej[16000000];      // fp16 embeddings
__device__ u16 g_Em[8000000];
__device__ float g_pJ[BJG * 17], g_pM[NBMG * 17];
__device__ float g_aV[NBG]; __device__ int g_aI[NBG]; __device__ float g_aS[NBG];
__device__ float g_g1[16], g_g2[16], g_ejs[16];
__device__ float g_logpj; __device__ int g_selj;
__device__ int g_c0, g_c1, g_c2, g_c3;
__device__ int g_s0, g_s1, g_s2, g_s3, g_s4, g_s5;

// ---------- packed f32x2 + fast math ----------
__device__ __forceinline__ u64 F2(u64 a, u64 b, u64 c) {
    u64 r; asm("fma.rn.f32x2 %0,%1,%2,%3;" : "=l"(r) : "l"(a), "l"(b), "l"(c)); return r;
}
__device__ __forceinline__ u64 pack2(float lo, float hi) {
    u64 r; asm("mov.b64 %0,{%1,%2};" : "=l"(r) : "f"(lo), "f"(hi)); return r;
}
__device__ __forceinline__ float2 unpack2(u64 v) {
    float2 r; asm("mov.b64 {%0,%1},%2;" : "=f"(r.x), "=f"(r.y) : "l"(v)); return r;
}
__device__ __forceinline__ float ftanh(float x) {
    float r; asm("tanh.approx.f32 %0,%1;" : "=f"(r) : "f"(x)); return r;
}
__device__ __forceinline__ unsigned f16x2(float lo, float hi) {   // first src = high half
    unsigned r; asm("cvt.rn.f16x2.f32 %0,%1,%2;" : "=r"(r) : "f"(hi), "f"(lo)); return r;
}
// u32 (two fp16) -> packed f32 pair
__device__ __forceinline__ u64 h2tof2(unsigned w) {
    float lo, hi;
    asm("{ .reg .f16 a,b;\n\t mov.b32 {a,b}, %2;\n\t cvt.f32.f16 %0,a;\n\t cvt.f32.f16 %1,b; }"
        : "=f"(lo), "=f"(hi) : "r"(w));
    return pack2(lo, hi);
}

// ---------- L2 eviction policies ----------
__device__ __forceinline__ u64 pol_evict_last() {
    u64 p; asm("createpolicy.fractional.L2::evict_last.b64 %0, 1.0;" : "=l"(p)); return p;
}
__device__ __forceinline__ u64 pol_evict_first() {
    u64 p; asm("createpolicy.fractional.L2::evict_first.b64 %0, 1.0;" : "=l"(p)); return p;
}

// ---------- bulk-async + mbarrier ----------
__device__ __forceinline__ unsigned s2u(const void* p) { return (unsigned)__cvta_generic_to_shared(p); }
__device__ __forceinline__ void mb_init(unsigned a, unsigned c) {
    asm volatile("mbarrier.init.shared.b64 [%0], %1;" :: "r"(a), "r"(c) : "memory");
}
__device__ __forceinline__ void mb_tx(unsigned a, unsigned bytes) {
    asm volatile("mbarrier.arrive.expect_tx.shared.b64 _, [%0], %1;" :: "r"(a), "r"(bytes) : "memory");
}
__device__ __forceinline__ void mb_wait(unsigned a, unsigned p) {
    asm volatile(
        "{\n\t.reg .pred P;\n"
        "WL%=:\n\t"
        "mbarrier.try_wait.parity.acquire.cta.shared::cta.b64 P, [%0], %1, 0x989680;\n\t"
        "@P bra WD%=;\n\t"
        "bra WL%=;\n"
        "WD%=:\n\t}"
        :: "r"(a), "r"(p) : "memory");
}
__device__ __forceinline__ void bulk_g2s(unsigned dst, const void* src, unsigned sz, unsigned mb, u64 pol) {
    asm volatile("cp.async.bulk.shared::cluster.global.mbarrier::complete_tx::bytes.L2::cache_hint "
                 "[%0], [%1], %2, [%3], %4;"
                 :: "r"(dst), "l"(src), "r"(sz), "r"(mb), "l"(pol) : "memory");
}
__device__ __forceinline__ void bulk_s2g(void* dst, unsigned src, unsigned sz, u64 pol) {
    asm volatile("cp.async.bulk.global.shared::cta.bulk_group.L2::cache_hint [%0], [%1], %2, %3;"
                 :: "l"(dst), "r"(src), "r"(sz), "l"(pol) : "memory");
}
__device__ __forceinline__ void bulk_commit() { asm volatile("cp.async.bulk.commit_group;" ::: "memory"); }
__device__ __forceinline__ void bulk_wait1() { asm volatile("cp.async.bulk.wait_group 1;" ::: "memory"); }
__device__ __forceinline__ void bulk_wait0() { asm volatile("cp.async.bulk.wait_group 0;" ::: "memory"); }
__device__ __forceinline__ void fence_async() { asm volatile("fence.proxy.async.shared::cta;" ::: "memory"); }

// fp32 64B row load (rotated quarters)
__device__ __forceinline__ void lds_row(unsigned sbase, int lr, u64 (&x)[8]) {
#pragma unroll
    for (int i = 0; i < 4; i++) {
        int q = (i + lr) & 3; u64 a, b;
        asm volatile("ld.shared.v2.b64 {%0,%1},[%2];" : "=l"(a), "=l"(b) : "r"(sbase + lr * 64 + q * 16));
        x[2 * q] = a; x[2 * q + 1] = b;
    }
}
// fp16 32B row load -> 8 packed f32 pairs (rotated halves)
__device__ __forceinline__ void lds_row_h(unsigned sbase, int lr, u64 (&x)[8]) {
    unsigned w[8];
#pragma unroll
    for (int i = 0; i < 2; i++) {
        int q = (i + lr) & 1;
        asm volatile("ld.shared.v4.b32 {%0,%1,%2,%3},[%4];"
                     : "=r"(w[4 * q]), "=r"(w[4 * q + 1]), "=r"(w[4 * q + 2]), "=r"(w[4 * q + 3])
                     : "r"(sbase + lr * 32 + q * 16));
    }
#pragma unroll
    for (int i = 0; i < 8; i++) x[i] = h2tof2(w[i]);
}
// fp16 32B row store (rotated halves)
__device__ __forceinline__ void sts_row_h(unsigned sbase, int lr, const unsigned (&w)[8]) {
#pragma unroll
    for (int i = 0; i < 2; i++) {
        int q = (i + lr) & 1;
        asm volatile("st.shared.v4.b32 [%0],{%1,%2,%3,%4};"
                     :: "r"(sbase + lr * 32 + q * 16),
                        "r"(w[4 * q]), "r"(w[4 * q + 1]), "r"(w[4 * q + 2]), "r"(w[4 * q + 3]) : "memory");
    }
}

__device__ __forceinline__ void redu17(float (&acc)[17], float* __restrict__ dst) {
#pragma unroll
    for (int k = 0; k < 17; k++)
#pragma unroll
        for (int o = 16; o > 0; o >>= 1) acc[k] += __shfl_down_sync(0xffffffffu, acc[k], o);
    __shared__ float red[4][17];
    int lane = threadIdx.x & 31, wid = threadIdx.x >> 5;
    if (lane == 0) {
#pragma unroll
        for (int k = 0; k < 17; k++) red[wid][k] = acc[k];
    }
    __syncthreads();
    if (threadIdx.x < 17) {
        float s = 0.f;
#pragma unroll
        for (int w = 0; w < 4; w++) s += red[w][threadIdx.x];
        dst[threadIdx.x] = s;
    }
}

// glimpse finalize (last block); scratch overlaid on dead input smem
struct FinGS { float tA[7][17]; float tB[7][17]; float sA[17]; float sB[17]; float cat[48]; float sGW[768]; };
__device__ void fin_g(int t, char* scr, const float* __restrict__ q0,
                      const float* __restrict__ gW, const float* __restrict__ gb,
                      float* __restrict__ dst, int* cnt) {
    FinGS* S = (FinGS*)scr;
    int col = t % 17, grp = t / 17;
    __syncthreads();
    if (grp < 7) {
        float a = 0.f, b = 0.f;
        for (int i = grp; i < BJG;  i += 7) a += g_pJ[i * 17 + col];
        for (int i = grp; i < NBMG; i += 7) b += g_pM[i * 17 + col];
        S->tA[grp][col] = a; S->tB[grp][col] = b;
    }
    for (int i = t; i < 768; i += BLOCK) S->sGW[i] = gW[i];
    __syncthreads();
    if (t < 17) {
        float a = 0.f, b = 0.f;
#pragma unroll
        for (int g = 0; g < 7; g++) { a += S->tA[g][t]; b += S->tB[g][t]; }
        S->sA[t] = a; S->sB[t] = b;
    }
    __syncthreads();
    if (t < 16) {
        S->cat[t] = q0[t];
        S->cat[16 + t] = S->sA[1 + t] / S->sA[0];
        S->cat[32 + t] = S->sB[1 + t] / S->sB[0];
    }
    __syncthreads();
    if (t < 16) {
        float g = gb[t];
#pragma unroll
        for (int d = 0; d < 48; d++) g += S->cat[d] * S->sGW[t * 48 + d];
        dst[t] = tanhf(g);
    }
    if (t == 0) *cnt = 0;
}

// argmax finalize; which==0 additionally recomputes e_js EXACTLY from raw jobs row
__device__ void fin_arg(int t, int which, float* __restrict__ out, int* cnt,
                        const float* __restrict__ jobsX,
                        const float* __restrict__ jW1, const float* __restrict__ jb1,
                        const float* __restrict__ jW2, const float* __restrict__ jb2) {
    float bv = -3e38f, s = 0.f; int bi = IMAXX;
    for (int i = t; i < NBG; i += BLOCK) {
        float v = g_aV[i]; int ix = g_aI[i];
        if (v > bv || (v == bv && ix < bi)) { bv = v; bi = ix; }
        s += g_aS[i];
    }
#pragma unroll
    for (int o = 16; o > 0; o >>= 1) {
        float ov = __shfl_down_sync(0xffffffffu, bv, o);
        int   oi = __shfl_down_sync(0xffffffffu, bi, o);
        s += __shfl_down_sync(0xffffffffu, s, o);
        if (ov > bv || (ov == bv && oi < bi)) { bv = ov; bi = oi; }
    }
    __shared__ float wv[4], ws[4]; __shared__ int wi[4]; __shared__ int ssel;
    __shared__ float hh[16];
    int lane = t & 31, wid = t >> 5;
    if (lane == 0) { wv[wid] = bv; wi[wid] = bi; ws[wid] = s; }
    __syncthreads();
    if (t == 0) {
        float v = wv[0]; int ix = wi[0]; float ss = ws[0];
#pragma unroll
        for (int w = 1; w < 4; w++) {
            if (wv[w] > v || (wv[w] == v && wi[w] < ix)) { v = wv[w]; ix = wi[w]; }
            ss += ws[w];
        }
        if (ix == IMAXX) ix = 0;
        if (which == 0) { g_selj = ix; g_logpj = v - logf(ss); ssel = ix; }
        else { out[0] = (float)g_selj; out[1] = (float)ix; out[2] = g_logpj + (v - logf(ss)); }
        *cnt = 0;
    }
    __syncthreads();
    if (which == 0) {
        // exact fp32 recompute of the selected job's embedding (matches k_emb's math)
        if (t < 16) {
            float a = jb1[t];
#pragma unroll
            for (int d = 0; d < 16; d++) a += jobsX[(size_t)ssel * 16 + d] * jW1[t * 16 + d];
            hh[t] = ftanh(a);
        }
        __syncthreads();
        if (t < 16) {
            float a = jb2[t];
#pragma unroll
            for (int d = 0; d < 16; d++) a += hh[d] * jW2[t * 16 + d];
            g_ejs[t] = ftanh(a);
        }
    }
}

// ================= pass 1: embed + glimpse-1 (work-stealing, fp16 E out) =================
#define CHE 128
#define CBE (CHE * 64)
#define OBE (CHE * 32)
__global__ void __launch_bounds__(BLOCK, 6) k_emb(
    const float* __restrict__ jobs, const float* __restrict__ machs, int Nj, int Nm,
    const float* __restrict__ jW1, const float* __restrict__ jb1,
    const float* __restrict__ jW2, const float* __restrict__ jb2,
    const float* __restrict__ mW1, const float* __restrict__ mb1,
    const float* __restrict__ mW2, const float* __restrict__ mb2,
    const float* __restrict__ ajWr, const float* __restrict__ ajV,
    const float* __restrict__ ajWq, const float* __restrict__ ajbq,
    const float* __restrict__ amWr, const float* __restrict__ amV,
    const float* __restrict__ amWq, const float* __restrict__ ambq,
    const float* __restrict__ lastj, const float* __restrict__ g1W, const float* __restrict__ g1b)
{
    __shared__ __align__(128) char inb[2][CBE];
    __shared__ __align__(128) char outb[2][OBE];
    __shared__ u64 mbs[2];
    __shared__ int sq[2];
    __shared__ ulonglong2 sW1[64], sW2[64], sWr[64];
    __shared__ float sb1[16], sb2[16], sV[16], sQ[16];

    int t = threadIdx.x;
    int side = blockIdx.x >= BJG;
    int lb = side ? blockIdx.x - BJG : blockIdx.x;
    const float* X = side ? machs : jobs;
    int N = side ? Nm : Nj;
    u16* Eo = side ? g_Em : g_Ej;
    float* part = (side ? g_pM : g_pJ) + lb * 17;
    int* sctr = side ? &g_s1 : &g_s0;
    const float* W1 = side ? mW1 : jW1; const float* b1 = side ? mb1 : jb1;
    const float* W2 = side ? mW2 : jW2; const float* b2 = side ? mb2 : jb2;
    const float* Wr = side ? amWr : ajWr; const float* V = side ? amV : ajV;
    const float* Wq = side ? amWq : ajWq; const float* bq = side ? ambq : ajbq;

    u64 pfirst = pol_evict_first();
    u64 plast  = pol_evict_last();

    if (t < 64) {
        sW1[t] = ((const ulonglong2*)W1)[t];
        sW2[t] = ((const ulonglong2*)W2)[t];
        sWr[t] = ((const ulonglong2*)Wr)[t];
    }
    if (t < 16) {
        sb1[t] = b1[t]; sb2[t] = b2[t]; sV[t] = V[t];
        float q = bq[t];
#pragma unroll
        for (int d = 0; d < 16; d++) q += lastj[d] * Wq[t * 16 + d];
        sQ[t] = q;
    }
    if (t == 0) { mb_init(s2u(&mbs[0]), 1); mb_init(s2u(&mbs[1]), 1); }
    __syncthreads();

    int nch = (N + CHE - 1) / CHE;
    if (t == 0) {
#pragma unroll
        for (int s = 0; s < 2; s++) {
            int c = atomicAdd(sctr, 1);
            sq[s] = (c < nch) ? c : IMAXX;
            if (c < nch) {
                int rows = N - c * CHE; if (rows > CHE) rows = CHE;
                mb_tx(s2u(&mbs[s]), rows * 64);
                bulk_g2s(s2u(&inb[s][0]), (const void*)(X + (size_t)c * CHE * 16), rows * 64, s2u(&mbs[s]), pfirst);
            }
        }
    }
    __syncthreads();

    float S = 0.f; u64 Wa[8];
#pragma unroll
    for (int k = 0; k < 8; k++) Wa[k] = 0ull;

    for (int k = 0; ; k++) {
        int s = k & 1;
        int c = sq[s];
        if (c == IMAXX) break;
        unsigned ph = (unsigned)((k >> 1) & 1);
        mb_wait(s2u(&mbs[s]), ph);

        int row0 = c * CHE;
        int rows = N - row0; if (rows > CHE) rows = CHE;
        bool ok = t < rows;
        u64 x[8], y[8]; unsigned eb[8];
        if (ok) lds_row(s2u(&inb[s][0]), t, x);
        else { for (int i = 0; i < 8; i++) x[i] = 0ull; }

        {   // layer 1
            float tp = 0.f;
#pragma unroll
            for (int j = 0; j < 16; j++) {
                u64 a = 0ull;
#pragma unroll
                for (int dd = 0; dd < 4; dd++) { ulonglong2 w = sW1[j * 4 + dd]; a = F2(x[2 * dd], w.x, a); a = F2(x[2 * dd + 1], w.y, a); }
                float2 u = unpack2(a); float tt = ftanh(u.x + u.y + sb1[j]);
                if (j & 1) y[j >> 1] = pack2(tp, tt); else tp = tt;
            }
        }
        {   // layer 2 -> embedding (f32 pairs in x, f16x2 in eb)
            float tp = 0.f;
#pragma unroll
            for (int j = 0; j < 16; j++) {
                u64 a = 0ull;
#pragma unroll
                for (int dd = 0; dd < 4; dd++) { ulonglong2 w = sW2[j * 4 + dd]; a = F2(y[2 * dd], w.x, a); a = F2(y[2 * dd + 1], w.y, a); }
                float2 u = unpack2(a); float tt = ftanh(u.x + u.y + sb2[j]);
                if (j & 1) { x[j >> 1] = pack2(tp, tt); eb[j >> 1] = f16x2(tp, tt); } else tp = tt;
            }
        }
        int os = k & 1;
        if (k >= 2 && t == 0) bulk_wait1();
        __syncthreads();
        if (ok) sts_row_h(s2u(&outb[os][0]), t, eb);
        fence_async();
        if (ok) {   // glimpse-1 (full f32 embedding)
            float l0 = 0.f, l1 = 0.f;
#pragma unroll
            for (int j = 0; j < 16; j++) {
                u64 a = 0ull;
#pragma unroll
                for (int dd = 0; dd < 4; dd++) { ulonglong2 w = sWr[j * 4 + dd]; a = F2(x[2 * dd], w.x, a); a = F2(x[2 * dd + 1], w.y, a); }
                float2 u = unpack2(a); float v = sV[j] * ftanh(u.x + u.y + sQ[j]);
                if (j & 1) l1 += v; else l0 += v;
            }
            float w = __expf(l0 + l1); S += w;
            u64 wp = pack2(w, w);
#pragma unroll
            for (int kk = 0; kk < 8; kk++) Wa[kk] = F2(wp, x[kk], Wa[kk]);
        }
        __syncthreads();
        if (t == 0) {
            bulk_s2g((void*)(Eo + (size_t)row0 * 16), s2u(&outb[os][0]), rows * 32, plast);
            bulk_commit();
            int cn = atomicAdd(sctr, 1);
            sq[s] = (cn < nch) ? cn : IMAXX;
            if (cn < nch) {
                int rn = N - cn * CHE; if (rn > CHE) rn = CHE;
                mb_tx(s2u(&mbs[s]), rn * 64);
                bulk_g2s(s2u(&inb[s][0]), (const void*)(X + (size_t)cn * CHE * 16), rn * 64, s2u(&mbs[s]), pfirst);
            }
        }
    }
    if (t == 0) bulk_wait0();

    float acc[17]; acc[0] = S;
#pragma unroll
    for (int k = 0; k < 8; k++) { float2 u = unpack2(Wa[k]); acc[1 + 2 * k] = u.x; acc[2 + 2 * k] = u.y; }
    redu17(acc, part);
    __syncthreads();
    __shared__ int lastb;
    if (t == 0) { __threadfence(); lastb = (atomicAdd(&g_c0, 1) == NBG - 1); }
    __syncthreads();
    if (lastb) {
        fin_g(t, &inb[0][0], lastj, g1W, g1b, g_g1, &g_c0);
        if (t == 0) { g_s0 = 0; g_s1 = 0; }
    }
}

// ================= pass 3: glimpse-2 over fp16 E (work-stealing, 4-stage) =================
#define CHR 128
#define CBR (CHR * 32)
__global__ void __launch_bounds__(BLOCK, 6) k_gl(
    int Nj, int Nm,
    const float* __restrict__ ajWr, const float* __restrict__ ajV,
    const float* __restrict__ ajWq, const float* __restrict__ ajbq,
    const float* __restrict__ amWr, const float* __restrict__ amV,
    const float* __restrict__ amWq, const float* __restrict__ ambq,
    const float* __restrict__ g2W, const float* __restrict__ g2b)
{
    __shared__ __align__(128) char inb[4][CBR];
    __shared__ u64 mbs[4];
    __shared__ int sq[4];
    __shared__ ulonglong2 sWr[64];
    __shared__ float sV[16], sQ[16];

    int t = threadIdx.x;
    int side = blockIdx.x >= BJG;
    int lb = side ? blockIdx.x - BJG : blockIdx.x;
    const u16* X = side ? g_Em : g_Ej;
    int N = side ? Nm : Nj;
    float* part = (side ? g_pM : g_pJ) + lb * 17;
    int* sctr = side ? &g_s4 : &g_s3;
    const float* Wr = side ? amWr : ajWr; const float* V = side ? amV : ajV;
    const float* Wq = side ? amWq : ajWq; const float* bq = side ? ambq : ajbq;

    u64 plast = pol_evict_last();

    if (t < 64) sWr[t] = ((const ulonglong2*)Wr)[t];
    if (t < 16) {
        sV[t] = V[t];
        float q = bq[t];
#pragma unroll
        for (int d = 0; d < 16; d++) q += g_ejs[d] * Wq[t * 16 + d];
        sQ[t] = q;
    }
    if (t == 0) {
#pragma unroll
        for (int s = 0; s < 4; s++) mb_init(s2u(&mbs[s]), 1);
    }
    __syncthreads();

    int nch = (N + CHR - 1) / CHR;
    if (t == 0) {
#pragma unroll
        for (int s = 0; s < 4; s++) {
            int c = atomicAdd(sctr, 1);
            sq[s] = (c < nch) ? c : IMAXX;
            if (c < nch) {
                int rows = N - c * CHR; if (rows > CHR) rows = CHR;
                mb_tx(s2u(&mbs[s]), rows * 32);
                bulk_g2s(s2u(&inb[s][0]), (const void*)(X + (size_t)c * CHR * 16), rows * 32, s2u(&mbs[s]), plast);
            }
        }
    }
    __syncthreads();

    float S = 0.f; u64 Wa[8];
#pragma unroll
    for (int k = 0; k < 8; k++) Wa[k] = 0ull;

    for (int k = 0; ; k++) {
        int s = k & 3;
        int c = sq[s];
        if (c == IMAXX) break;
        unsigned ph = (unsigned)((k >> 2) & 1);
        mb_wait(s2u(&mbs[s]), ph);

        int row0 = c * CHR;
        int rows = N - row0; if (rows > CHR) rows = CHR;
        if (t < rows) {
            u64 x[8];
            lds_row_h(s2u(&inb[s][0]), t, x);
            float l0 = 0.f, l1 = 0.f;
#pragma unroll
            for (int j = 0; j < 16; j++) {
                u64 a = 0ull;
#pragma unroll
                for (int dd = 0; dd < 4; dd++) { ulonglong2 w = sWr[j * 4 + dd]; a = F2(x[2 * dd], w.x, a); a = F2(x[2 * dd + 1], w.y, a); }
                float2 u = unpack2(a); float v = sV[j] * ftanh(u.x + u.y + sQ[j]);
                if (j & 1) l1 += v; else l0 += v;
            }
            float w = __expf(l0 + l1); S += w;
            u64 wp = pack2(w, w);
#pragma unroll
            for (int kk = 0; kk < 8; kk++) Wa[kk] = F2(wp, x[kk], Wa[kk]);
        }
        __syncthreads();
        if (t == 0) {
            int cn = atomicAdd(sctr, 1);
            sq[s] = (cn < nch) ? cn : IMAXX;
            if (cn < nch) {
                int rn = N - cn * CHR; if (rn > CHR) rn = CHR;
                mb_tx(s2u(&mbs[s]), rn * 32);
                bulk_g2s(s2u(&inb[s][0]), (const void*)(X + (size_t)cn * CHR * 16), rn * 32, s2u(&mbs[s]), plast);
            }
        }
    }

    float acc[17]; acc[0] = S;
#pragma unroll
    for (int k = 0; k < 8; k++) { float2 u = unpack2(Wa[k]); acc[1 + 2 * k] = u.x; acc[2 + 2 * k] = u.y; }
    redu17(acc, part);
    __syncthreads();
    __shared__ int lastb;
    if (t == 0) { __threadfence(); lastb = (atomicAdd(&g_c2, 1) == NBG - 1); }
    __syncthreads();
    if (lastb) {
        fin_g(t, &inb[0][0], g_ejs, g2W, g2b, g_g2, &g_c2);
        if (t == 0) { g_s3 = 0; g_s4 = 0; }
    }
}

// ================= passes 2 & 4: pointer logits over fp16 E =================
__global__ void __launch_bounds__(BLOCK, 6) k_arg(
    int which, int N,
    const float* __restrict__ Wr, const float* __restrict__ V,
    const float* __restrict__ Wq, const float* __restrict__ bq,
    const void* __restrict__ maskp, int nmask, float* __restrict__ out,
    const float* __restrict__ jobsX,
    const float* __restrict__ jW1, const float* __restrict__ jb1,
    const float* __restrict__ jW2, const float* __restrict__ jb2)
{
    __shared__ __align__(128) char inb[4][CBR];
    __shared__ u64 mbs[4];
    __shared__ int sq[4];
    __shared__ ulonglong2 sWr[64];
    __shared__ float sV[16], sQ[16];
    __shared__ int smk;

    int t = threadIdx.x;
    const u16* X = which ? g_Em : g_Ej;
    const float* qs = which ? g_g2 : g_g1;
    int* cnt = which ? &g_c3 : &g_c1;
    int* sctr = which ? &g_s5 : &g_s2;

    u64 plast = pol_evict_last();

    if (t == 0) smk = 0;
    if (t < 64) sWr[t] = ((const ulonglong2*)Wr)[t];
    if (t < 16) {
        sV[t] = V[t];
        float q = bq[t];
#pragma unroll
        for (int d = 0; d < 16; d++) q += qs[d] * Wq[t * 16 + d];
        sQ[t] = q;
    }
    if (t == 0) {
#pragma unroll
        for (int s = 0; s < 4; s++) mb_init(s2u(&mbs[s]), 1);
    }
    __syncthreads();
    // mask dtype detect: 0 = 4-byte elems, 1 = byte bools
    if (maskp) {
        int words = nmask >> 2; if (words > 4096) words = 4096;
        int f = 0;
        for (int i = t; i < words; i += BLOCK) {
            unsigned w = ((const unsigned*)maskp)[i];
            if (w != 0u && w != 1u && w != 0x3F800000u) f = 1;
        }
        if (f) atomicOr(&smk, 1);
    }
    __syncthreads();
    int mk = smk;

    int nch = (N + CHR - 1) / CHR;
    if (t == 0) {
#pragma unroll
        for (int s = 0; s < 4; s++) {
            int c = atomicAdd(sctr, 1);
            sq[s] = (c < nch) ? c : IMAXX;
            if (c < nch) {
                int rows = N - c * CHR; if (rows > CHR) rows = CHR;
                mb_tx(s2u(&mbs[s]), rows * 32);
                bulk_g2s(s2u(&inb[s][0]), (const void*)(X + (size_t)c * CHR * 16), rows * 32, s2u(&mbs[s]), plast);
            }
        }
    }
    __syncthreads();

    float best = -3e38f, sum = 0.f; int bi = IMAXX;
    for (int k = 0; ; k++) {
        int s = k & 3;
        int c = sq[s];
        if (c == IMAXX) break;
        unsigned ph = (unsigned)((k >> 2) & 1);
        mb_wait(s2u(&mbs[s]), ph);

        int row0 = c * CHR;
        int rows = N - row0; if (rows > CHR) rows = CHR;
        if (t < rows) {
            u64 x[8];
            lds_row_h(s2u(&inb[s][0]), t, x);
            float l0 = 0.f, l1 = 0.f;
#pragma unroll
            for (int j = 0; j < 16; j++) {
                u64 a = 0ull;
#pragma unroll
                for (int dd = 0; dd < 4; dd++) { ulonglong2 w = sWr[j * 4 + dd]; a = F2(x[2 * dd], w.x, a); a = F2(x[2 * dd + 1], w.y, a); }
                float2 u = unpack2(a); float v = sV[j] * ftanh(u.x + u.y + sQ[j]);
                if (j & 1) l1 += v; else l0 += v;
            }
            float l = l0 + l1;
            int row = row0 + t;
            bool pass = true;
            if (maskp) {
                if (mk) pass = ((const unsigned char*)maskp)[row] != 0;
                else    pass = ((const unsigned*)maskp)[row] != 0u;
            }
            if (pass) {
                sum += __expf(l);
                if (l > best) { best = l; bi = row; }
            }
        }
        __syncthreads();
        if (t == 0) {
            int cn = atomicAdd(sctr, 1);
            sq[s] = (cn < nch) ? cn : IMAXX;
            if (cn < nch) {
                int rn = N - cn * CHR; if (rn > CHR) rn = CHR;
                mb_tx(s2u(&mbs[s]), rn * 32);
                bulk_g2s(s2u(&inb[s][0]), (const void*)(X + (size_t)cn * CHR * 16), rn * 32, s2u(&mbs[s]), plast);
            }
        }
    }
#pragma unroll
    for (int of = 16; of > 0; of >>= 1) {
        float ov = __shfl_down_sync(0xffffffffu, best, of);
        int   oi = __shfl_down_sync(0xffffffffu, bi, of);
        sum += __shfl_down_sync(0xffffffffu, sum, of);
        if (ov > best || (ov == best && oi < bi)) { best = ov; bi = oi; }
    }
    __shared__ float wv[4], ws[4]; __shared__ int wi[4];
    int lane = t & 31, wid = t >> 5;
    if (lane == 0) { wv[wid] = best; wi[wid] = bi; ws[wid] = sum; }
    __syncthreads();
    if (t == 0) {
        float v = wv[0]; int ix = wi[0]; float s = ws[0];
#pragma unroll
        for (int w = 1; w < 4; w++) {
            if (wv[w] > v || (wv[w] == v && wi[w] < ix)) { v = wv[w]; ix = wi[w]; }
            s += ws[w];
        }
        g_aV[blockIdx.x] = v; g_aI[blockIdx.x] = ix; g_aS[blockIdx.x] = s;
    }
    __syncthreads();
    __shared__ int lastb;
    if (t == 0) { __threadfence(); lastb = (atomicAdd(cnt, 1) == NBG - 1); }
    __syncthreads();
    if (lastb) {
        fin_arg(t, which, out, cnt, jobsX, jW1, jb1, jW2, jb2);
        if (t == 0) { if (which) g_s5 = 0; else g_s2 = 0; }
    }
}

extern "C" void kernel_launch(void* const* d_in, const int* in_sizes, int n_in,
                              void* d_out, int out_size) {
    const float* jobs  = (const float*)d_in[0];
    const float* machs = (const float*)d_in[1];
    const void*  mask  = d_in[2];
    const float *jW1=(const float*)d_in[3], *jb1=(const float*)d_in[4], *jW2=(const float*)d_in[5], *jb2=(const float*)d_in[6];
    const float *mW1=(const float*)d_in[7], *mb1=(const float*)d_in[8], *mW2=(const float*)d_in[9], *mb2=(const float*)d_in[10];
    const float *ajWq=(const float*)d_in[11], *ajbq=(const float*)d_in[12], *ajWr=(const float*)d_in[13], *ajV=(const float*)d_in[14];
    const float *amWq=(const float*)d_in[15], *ambq=(const float*)d_in[16], *amWr=(const float*)d_in[17], *amV=(const float*)d_in[18];
    const float *jaWq=(const float*)d_in[19], *jabq=(const float*)d_in[20], *jaWr=(const float*)d_in[21], *jaV=(const float*)d_in[22];
    const float *maWq=(const float*)d_in[23], *mabq=(const float*)d_in[24], *maWr=(const float*)d_in[25], *maV=(const float*)d_in[26];
    const float *g1W=(const float*)d_in[27], *g1b=(const float*)d_in[28];
    const float *g2W=(const float*)d_in[29], *g2b=(const float*)d_in[30];
    const float *lastj=(const float*)d_in[31];
    int Nj = in_sizes[0] / 16;
    int Nm = in_sizes[1] / 16;
    float* out = (float*)d_out;

    k_emb<<<NBG, BLOCK>>>(jobs, machs, Nj, Nm, jW1, jb1, jW2, jb2, mW1, mb1, mW2, mb2,
                          ajWr, ajV, ajWq, ajbq, amWr, amV, amWq, ambq, lastj, g1W, g1b);
    k_arg<<<NBG, BLOCK>>>(0, Nj, jaWr, jaV, jaWq, jabq, mask, in_sizes[2], out,
                          jobs, jW1, jb1, jW2, jb2);
    k_gl <<<NBG, BLOCK>>>(Nj, Nm, ajWr, ajV, ajWq, ajbq, amWr, amV, amWq, ambq, g2W, g2b);
    k_arg<<<NBG, BLOCK>>>(1, Nm, maWr, maV, maWq, mabq, nullptr, 0, out,
                          nullptr, nullptr, nullptr, nullptr, nullptr);
    (void)n_in; (void)out_size;
}

// round 14
// speedup vs baseline: 1.4705x; 1.1166x over previous
#include <cuda_runtime.h>
#include <math.h>

#define BLOCK 128
#define NBE 592
#define BJE 396
#define NBME (NBE - BJE)
#define NBL 740
#define BJL 494
#define NBML (NBL - BJL)
#define NBA 888
#define IMAXX 0x7fffffff
typedef unsigned long long u64;
typedef unsigned short u16;

__device__ u16 g_Ej[16000000];
__device__ u16 g_Em[8000000];
__device__ float g_pJ[BJL * 17], g_pM[NBML * 17];
__device__ float g_aV[NBA]; __device__ int g_aI[NBA]; __device__ float g_aS[NBA];
__device__ float g_g1[16], g_g2[16], g_ejs[16];
__device__ float g_logpj; __device__ int g_selj;
__device__ int g_c0, g_c1, g_c2, g_c3;
__device__ int g_s0, g_s1, g_s2, g_s3, g_s4, g_s5;

__device__ __forceinline__ u64 F2(u64 a, u64 b, u64 c) {
    u64 r; asm("fma.rn.f32x2 %0,%1,%2,%3;" : "=l"(r) : "l"(a), "l"(b), "l"(c)); return r;
}
__device__ __forceinline__ u64 pack2(float lo, float hi) {
    u64 r; asm("mov.b64 %0,{%1,%2};" : "=l"(r) : "f"(lo), "f"(hi)); return r;
}
__device__ __forceinline__ float2 unpack2(u64 v) {
    float2 r; asm("mov.b64 {%0,%1},%2;" : "=f"(r.x), "=f"(r.y) : "l"(v)); return r;
}
__device__ __forceinline__ float ftanh(float x) {
    float r; asm("tanh.approx.f32 %0,%1;" : "=f"(r) : "f"(x)); return r;
}
__device__ __forceinline__ unsigned f16x2(float lo, float hi) {
    unsigned r; asm("cvt.rn.f16x2.f32 %0,%1,%2;" : "=r"(r) : "f"(hi), "f"(lo)); return r;
}
__device__ __forceinline__ u64 h2tof2(unsigned w) {
    float lo, hi;
    asm("{ .reg .f16 a,b;\n\t mov.b32 {a,b}, %2;\n\t cvt.f32.f16 %0,a;\n\t cvt.f32.f16 %1,b; }"
        : "=f"(lo), "=f"(hi) : "r"(w));
    return pack2(lo, hi);
}
__device__ __forceinline__ u64 pol_evict_last() {
    u64 p; asm("createpolicy.fractional.L2::evict_last.b64 %0, 1.0;" : "=l"(p)); return p;
}
__device__ __forceinline__ u64 pol_evict_first() {
    u64 p; asm("createpolicy.fractional.L2::evict_first.b64 %0, 1.0;" : "=l"(p)); return p;
}
__device__ __forceinline__ unsigned s2u(const void* p) { return (unsigned)__cvta_generic_to_shared(p); }
__device__ __forceinline__ void mb_init(unsigned a, unsigned c) {
    asm volatile("mbarrier.init.shared.b64 [%0], %1;" :: "r"(a), "r"(c) : "memory");
}
__device__ __forceinline__ void mb_tx(unsigned a, unsigned bytes) {
    asm volatile("mbarrier.arrive.expect_tx.shared.b64 _, [%0], %1;" :: "r"(a), "r"(bytes) : "memory");
}
__device__ __forceinline__ void mb_wait(unsigned a, unsigned p) {
    asm volatile(
        "{\n\t.reg .pred P;\n"
        "WL%=:\n\t"
        "mbarrier.try_wait.parity.acquire.cta.shared::cta.b64 P, [%0], %1, 0x989680;\n\t"
        "@P bra WD%=;\n\t"
        "bra WL%=;\n"
        "WD%=:\n\t}"
        :: "r"(a), "r"(p) : "memory");
}
__device__ __forceinline__ void bulk_g2s(unsigned dst, const void* src, unsigned sz, unsigned mb, u64 pol) {
    asm volatile("cp.async.bulk.shared::cluster.global.mbarrier::complete_tx::bytes.L2::cache_hint "
                 "[%0], [%1], %2, [%3], %4;"
                 :: "r"(dst), "l"(src), "r"(sz), "r"(mb), "l"(pol) : "memory");
}
__device__ __forceinline__ void bulk_s2g(void* dst, unsigned src, unsigned sz, u64 pol) {
    asm volatile("cp.async.bulk.global.shared::cta.bulk_group.L2::cache_hint [%0], [%1], %2, %3;"
                 :: "l"(dst), "r"(src), "r"(sz), "l"(pol) : "memory");
}
__device__ __forceinline__ void bulk_commit() { asm volatile("cp.async.bulk.commit_group;" ::: "memory"); }
__device__ __forceinline__ void bulk_wait1() { asm volatile("cp.async.bulk.wait_group 1;" ::: "memory"); }
__device__ __forceinline__ void bulk_wait0() { asm volatile("cp.async.bulk.wait_group 0;" ::: "memory"); }
__device__ __forceinline__ void fence_async() { asm volatile("fence.proxy.async.shared::cta;" ::: "memory"); }

__device__ __forceinline__ void lds_row(unsigned sbase, int lr, u64 (&x)[8]) {
#pragma unroll
    for (int i = 0; i < 4; i++) {
        int q = (i + lr) & 3; u64 a, b;
        asm volatile("ld.shared.v2.b64 {%0,%1},[%2];" : "=l"(a), "=l"(b) : "r"(sbase + lr * 64 + q * 16));
        x[2 * q] = a; x[2 * q + 1] = b;
    }
}
__device__ __forceinline__ void lds_row_h(unsigned sbase, int lr, u64 (&x)[8]) {
    unsigned w[8];
#pragma unroll
    for (int i = 0; i < 2; i++) {
        int q = (i + lr) & 1;
        asm volatile("ld.shared.v4.b32 {%0,%1,%2,%3},[%4];"
                     : "=r"(w[4 * q]), "=r"(w[4 * q + 1]), "=r"(w[4 * q + 2]), "=r"(w[4 * q + 3])
                     : "r"(sbase + lr * 32 + q * 16));
    }
#pragma unroll
    for (int i = 0; i < 8; i++) x[i] = h2tof2(w[i]);
}
__device__ __forceinline__ void sts_row_h(unsigned sbase, int lr, const unsigned (&w)[8]) {
#pragma unroll
    for (int i = 0; i < 2; i++) {
        int q = (i + lr) & 1;
        asm volatile("st.shared.v4.b32 [%0],{%1,%2,%3,%4};"
                     :: "r"(sbase + lr * 32 + q * 16),
                        "r"(w[4 * q]), "r"(w[4 * q + 1]), "r"(w[4 * q + 2]), "r"(w[4 * q + 3]) : "memory");
    }
}

__device__ __forceinline__ void redu17(float (&acc)[17], float* __restrict__ dst) {
#pragma unroll
    for (int k = 0; k < 17; k++)
#pragma unroll
        for (int o = 16; o > 0; o >>= 1) acc[k] += __shfl_down_sync(0xffffffffu, acc[k], o);
    __shared__ float red[4][17];
    int lane = threadIdx.x & 31, wid = threadIdx.x >> 5;
    if (lane == 0) {
#pragma unroll
        for (int k = 0; k < 17; k++) red[wid][k] = acc[k];
    }
    __syncthreads();
    if (threadIdx.x < 17) {
        float s = 0.f;
#pragma unroll
        for (int w = 0; w < 4; w++) s += red[w][threadIdx.x];
        dst[threadIdx.x] = s;
    }
}

struct FinGS { float tA[7][17]; float tB[7][17]; float sA[17]; float sB[17]; float cat[48]; float sGW[768]; };
__device__ void fin_g(int t, char* scr, int bj, int nbm, const float* __restrict__ q0,
                      const float* __restrict__ gW, const float* __restrict__ gb,
                      float* __restrict__ dst, int* cnt) {
    FinGS* S = (FinGS*)scr;
    int col = t % 17, grp = t / 17;
    __syncthreads();
    if (grp < 7) {
        float a = 0.f, b = 0.f;
        for (int i = grp; i < bj;  i += 7) a += g_pJ[i * 17 + col];
        for (int i = grp; i < nbm; i += 7) b += g_pM[i * 17 + col];
        S->tA[grp][col] = a; S->tB[grp][col] = b;
    }
    for (int i = t; i < 768; i += BLOCK) S->sGW[i] = gW[i];
    __syncthreads();
    if (t < 17) {
        float a = 0.f, b = 0.f;
#pragma unroll
        for (int g = 0; g < 7; g++) { a += S->tA[g][t]; b += S->tB[g][t]; }
        S->sA[t] = a; S->sB[t] = b;
    }
    __syncthreads();
    if (t < 16) {
        S->cat[t] = q0[t];
        S->cat[16 + t] = S->sA[1 + t] / S->sA[0];
        S->cat[32 + t] = S->sB[1 + t] / S->sB[0];
    }
    __syncthreads();
    if (t < 16) {
        float g = gb[t];
#pragma unroll
        for (int d = 0; d < 48; d++) g += S->cat[d] * S->sGW[t * 48 + d];
        dst[t] = tanhf(g);
    }
    if (t == 0) *cnt = 0;
}

__device__ void fin_arg(int t, int which, float* __restrict__ out, int* cnt,
                        const float* __restrict__ jobsX,
                        const float* __restrict__ jW1, const float* __restrict__ jb1,
                        const float* __restrict__ jW2, const float* __restrict__ jb2) {
    float bv = -3e38f, s = 0.f; int bi = IMAXX;
    for (int i = t; i < NBA; i += BLOCK) {
        float v = g_aV[i]; int ix = g_aI[i];
        if (v > bv || (v == bv && ix < bi)) { bv = v; bi = ix; }
        s += g_aS[i];
    }
#pragma unroll
    for (int o = 16; o > 0; o >>= 1) {
        float ov = __shfl_down_sync(0xffffffffu, bv, o);
        int   oi = __shfl_down_sync(0xffffffffu, bi, o);
        s += __shfl_down_sync(0xffffffffu, s, o);
        if (ov > bv || (ov == bv && oi < bi)) { bv = ov; bi = oi; }
    }
    __shared__ float wv[4], ws[4]; __shared__ int wi[4]; __shared__ int ssel;
    __shared__ float hh[16];
    int lane = t & 31, wid = t >> 5;
    if (lane == 0) { wv[wid] = bv; wi[wid] = bi; ws[wid] = s; }
    __syncthreads();
    if (t == 0) {
        float v = wv[0]; int ix = wi[0]; float ss = ws[0];
#pragma unroll
        for (int w = 1; w < 4; w++) {
            if (wv[w] > v || (wv[w] == v && wi[w] < ix)) { v = wv[w]; ix = wi[w]; }
            ss += ws[w];
        }
        if (ix == IMAXX) ix = 0;
        if (which == 0) { g_selj = ix; g_logpj = v - logf(ss); ssel = ix; }
        else { out[0] = (float)g_selj; out[1] = (float)ix; out[2] = g_logpj + (v - logf(ss)); }
        *cnt = 0;
    }
    __syncthreads();
    if (which == 0) {
        if (t < 16) {
            float a = jb1[t];
#pragma unroll
            for (int d = 0; d < 16; d++) a += jobsX[(size_t)ssel * 16 + d] * jW1[t * 16 + d];
            hh[t] = ftanh(a);
        }
        __syncthreads();
        if (t < 16) {
            float a = jb2[t];
#pragma unroll
            for (int d = 0; d < 16; d++) a += hh[d] * jW2[t * 16 + d];
            g_ejs[t] = ftanh(a);
        }
    }
}

// ================= pass 1: embed + glimpse-1 (2 rows/thread, chunk 256) =================
#define CHE 256
#define CBE (CHE * 64)
#define OBE (CHE * 32)
__global__ void __launch_bounds__(BLOCK, 4) k_emb(
    const float* __restrict__ jobs, const float* __restrict__ machs, int Nj, int Nm,
    const float* __restrict__ jW1, const float* __restrict__ jb1,
    const float* __restrict__ jW2, const float* __restrict__ jb2,
    const float* __restrict__ mW1, const float* __restrict__ mb1,
    const float* __restrict__ mW2, const float* __restrict__ mb2,
    const float* __restrict__ ajWr, const float* __restrict__ ajV,
    const float* __restrict__ ajWq, const float* __restrict__ ajbq,
    const float* __restrict__ amWr, const float* __restrict__ amV,
    const float* __restrict__ amWq, const float* __restrict__ ambq,
    const float* __restrict__ lastj, const float* __restrict__ g1W, const float* __restrict__ g1b)
{
    __shared__ __align__(128) char inb[2][CBE];
    __shared__ __align__(128) char outb[2][OBE];
    __shared__ u64 mbs[2];
    __shared__ int sq[2];
    __shared__ ulonglong2 sW1[64], sW2[64], sWr[64];
    __shared__ float sb1[16], sb2[16], sV[16], sQ[16];

    int t = threadIdx.x;
    int side = blockIdx.x >= BJE;
    int lb = side ? blockIdx.x - BJE : blockIdx.x;
    const float* X = side ? machs : jobs;
    int N = side ? Nm : Nj;
    u16* Eo = side ? g_Em : g_Ej;
    float* part = (side ? g_pM : g_pJ) + lb * 17;
    int* sctr = side ? &g_s1 : &g_s0;
    const float* W1 = side ? mW1 : jW1; const float* b1 = side ? mb1 : jb1;
    const float* W2 = side ? mW2 : jW2; const float* b2 = side ? mb2 : jb2;
    const float* Wr = side ? amWr : ajWr; const float* V = side ? amV : ajV;
    const float* Wq = side ? amWq : ajWq; const float* bq = side ? ambq : ajbq;

    u64 pfirst = pol_evict_first();
    u64 plast  = pol_evict_last();

    if (t < 64) {
        sW1[t] = ((const ulonglong2*)W1)[t];
        sW2[t] = ((const ulonglong2*)W2)[t];
        sWr[t] = ((const ulonglong2*)Wr)[t];
    }
    if (t < 16) {
        sb1[t] = b1[t]; sb2[t] = b2[t]; sV[t] = V[t];
        float q = bq[t];
#pragma unroll
        for (int d = 0; d < 16; d++) q += lastj[d] * Wq[t * 16 + d];
        sQ[t] = q;
    }
    if (t == 0) { mb_init(s2u(&mbs[0]), 1); mb_init(s2u(&mbs[1]), 1); }
    __syncthreads();

    int nch = (N + CHE - 1) / CHE;
    if (t == 0) {
#pragma unroll
        for (int s = 0; s < 2; s++) {
            int c = atomicAdd(sctr, 1);
            sq[s] = (c < nch) ? c : IMAXX;
            if (c < nch) {
                int rows = N - c * CHE; if (rows > CHE) rows = CHE;
                mb_tx(s2u(&mbs[s]), rows * 64);
                bulk_g2s(s2u(&inb[s][0]), (const void*)(X + (size_t)c * CHE * 16), rows * 64, s2u(&mbs[s]), pfirst);
            }
        }
    }
    __syncthreads();

    float S = 0.f; u64 Wa[8];
#pragma unroll
    for (int k = 0; k < 8; k++) Wa[k] = 0ull;

    for (int k = 0; ; k++) {
        int s = k & 1;
        int c = sq[s];
        if (c == IMAXX) break;
        unsigned ph = (unsigned)((k >> 1) & 1);
        mb_wait(s2u(&mbs[s]), ph);

        int row0 = c * CHE;
        int rows = N - row0; if (rows > CHE) rows = CHE;
        bool ok0 = t < rows, ok1 = t + BLOCK < rows;
        u64 x0[8], x1[8], y0[8], y1[8]; unsigned e0[8], e1[8];
        if (ok0) lds_row(s2u(&inb[s][0]), t, x0); else { for (int i = 0; i < 8; i++) x0[i] = 0ull; }
        if (ok1) lds_row(s2u(&inb[s][0]), t + BLOCK, x1); else { for (int i = 0; i < 8; i++) x1[i] = 0ull; }

        {   // layer 1 (shared weight loads)
            float tp0 = 0.f, tp1 = 0.f;
#pragma unroll
            for (int j = 0; j < 16; j++) {
                u64 a0 = 0ull, a1 = 0ull;
#pragma unroll
                for (int dd = 0; dd < 4; dd++) {
                    ulonglong2 w = sW1[j * 4 + dd];
                    a0 = F2(x0[2 * dd], w.x, a0); a0 = F2(x0[2 * dd + 1], w.y, a0);
                    a1 = F2(x1[2 * dd], w.x, a1); a1 = F2(x1[2 * dd + 1], w.y, a1);
                }
                float2 u0 = unpack2(a0), u1 = unpack2(a1); float b = sb1[j];
                float v0 = ftanh(u0.x + u0.y + b), v1 = ftanh(u1.x + u1.y + b);
                if (j & 1) { y0[j >> 1] = pack2(tp0, v0); y1[j >> 1] = pack2(tp1, v1); }
                else { tp0 = v0; tp1 = v1; }
            }
        }
        {   // layer 2 -> embeddings
            float tp0 = 0.f, tp1 = 0.f;
#pragma unroll
            for (int j = 0; j < 16; j++) {
                u64 a0 = 0ull, a1 = 0ull;
#pragma unroll
                for (int dd = 0; dd < 4; dd++) {
                    ulonglong2 w = sW2[j * 4 + dd];
                    a0 = F2(y0[2 * dd], w.x, a0); a0 = F2(y0[2 * dd + 1], w.y, a0);
                    a1 = F2(y1[2 * dd], w.x, a1); a1 = F2(y1[2 * dd + 1], w.y, a1);
                }
                float2 u0 = unpack2(a0), u1 = unpack2(a1); float b = sb2[j];
                float v0 = ftanh(u0.x + u0.y + b), v1 = ftanh(u1.x + u1.y + b);
                if (j & 1) {
                    x0[j >> 1] = pack2(tp0, v0); e0[j >> 1] = f16x2(tp0, v0);
                    x1[j >> 1] = pack2(tp1, v1); e1[j >> 1] = f16x2(tp1, v1);
                } else { tp0 = v0; tp1 = v1; }
            }
        }
        int os = k & 1;
        if (k >= 2 && t == 0) bulk_wait1();
        __syncthreads();
        if (ok0) sts_row_h(s2u(&outb[os][0]), t, e0);
        if (ok1) sts_row_h(s2u(&outb[os][0]), t + BLOCK, e1);
        fence_async();
        {   // glimpse-1, both rows, shared sWr loads
            float l00 = 0.f, l01 = 0.f, l10 = 0.f, l11 = 0.f;
#pragma unroll
            for (int j = 0; j < 16; j++) {
                u64 a0 = 0ull, a1 = 0ull;
#pragma unroll
                for (int dd = 0; dd < 4; dd++) {
                    ulonglong2 w = sWr[j * 4 + dd];
                    a0 = F2(x0[2 * dd], w.x, a0); a0 = F2(x0[2 * dd + 1], w.y, a0);
                    a1 = F2(x1[2 * dd], w.x, a1); a1 = F2(x1[2 * dd + 1], w.y, a1);
                }
                float2 u0 = unpack2(a0), u1 = unpack2(a1); float vj = sV[j], qj = sQ[j];
                float v0 = vj * ftanh(u0.x + u0.y + qj), v1 = vj * ftanh(u1.x + u1.y + qj);
                if (j & 1) { l01 += v0; l11 += v1; } else { l00 += v0; l10 += v1; }
            }
            if (ok0) {
                float w = __expf(l00 + l01); S += w; u64 wp = pack2(w, w);
#pragma unroll
                for (int kk = 0; kk < 8; kk++) Wa[kk] = F2(wp, x0[kk], Wa[kk]);
            }
            if (ok1) {
                float w = __expf(l10 + l11); S += w; u64 wp = pack2(w, w);
#pragma unroll
                for (int kk = 0; kk < 8; kk++) Wa[kk] = F2(wp, x1[kk], Wa[kk]);
            }
        }
        __syncthreads();
        if (t == 0) {
            bulk_s2g((void*)(Eo + (size_t)row0 * 16), s2u(&outb[os][0]), rows * 32, plast);
            bulk_commit();
            int cn = atomicAdd(sctr, 1);
            sq[s] = (cn < nch) ? cn : IMAXX;
            if (cn < nch) {
                int rn = N - cn * CHE; if (rn > CHE) rn = CHE;
                mb_tx(s2u(&mbs[s]), rn * 64);
                bulk_g2s(s2u(&inb[s][0]), (const void*)(X + (size_t)cn * CHE * 16), rn * 64, s2u(&mbs[s]), pfirst);
            }
        }
    }
    if (t == 0) bulk_wait0();

    float acc[17]; acc[0] = S;
#pragma unroll
    for (int k = 0; k < 8; k++) { float2 u = unpack2(Wa[k]); acc[1 + 2 * k] = u.x; acc[2 + 2 * k] = u.y; }
    redu17(acc, part);
    __syncthreads();
    __shared__ int lastb;
    if (t == 0) { __threadfence(); lastb = (atomicAdd(&g_c0, 1) == NBE - 1); }
    __syncthreads();
    if (lastb) {
        fin_g(t, &inb[0][0], BJE, NBME, lastj, g1W, g1b, g_g1, &g_c0);
        if (t == 0) { g_s0 = 0; g_s1 = 0; }
    }
}

// ================= pass 3: glimpse-2 over fp16 E (2 rows/thread, chunk 256, 3-stage) =================
#define CHR 256
#define CBR (CHR * 32)
__global__ void __launch_bounds__(BLOCK, 5) k_gl(
    int Nj, int Nm,
    const float* __restrict__ ajWr, const float* __restrict__ ajV,
    const float* __restrict__ ajWq, const float* __restrict__ ajbq,
    const float* __restrict__ amWr, const float* __restrict__ amV,
    const float* __restrict__ amWq, const float* __restrict__ ambq,
    const float* __restrict__ g2W, const float* __restrict__ g2b)
{
    __shared__ __align__(128) char inb[3][CBR];
    __shared__ u64 mbs[3];
    __shared__ int sq[3];
    __shared__ ulonglong2 sWr[64];
    __shared__ float sV[16], sQ[16];

    int t = threadIdx.x;
    int side = blockIdx.x >= BJL;
    int lb = side ? blockIdx.x - BJL : blockIdx.x;
    const u16* X = side ? g_Em : g_Ej;
    int N = side ? Nm : Nj;
    float* part = (side ? g_pM : g_pJ) + lb * 17;
    int* sctr = side ? &g_s4 : &g_s3;
    const float* Wr = side ? amWr : ajWr; const float* V = side ? amV : ajV;
    const float* Wq = side ? amWq : ajWq; const float* bq = side ? ambq : ajbq;

    u64 plast = pol_evict_last();

    if (t < 64) sWr[t] = ((const ulonglong2*)Wr)[t];
    if (t < 16) {
        sV[t] = V[t];
        float q = bq[t];
#pragma unroll
        for (int d = 0; d < 16; d++) q += g_ejs[d] * Wq[t * 16 + d];
        sQ[t] = q;
    }
    if (t == 0) {
#pragma unroll
        for (int s = 0; s < 3; s++) mb_init(s2u(&mbs[s]), 1);
    }
    __syncthreads();

    int nch = (N + CHR - 1) / CHR;
    if (t == 0) {
#pragma unroll
        for (int s = 0; s < 3; s++) {
            int c = atomicAdd(sctr, 1);
            sq[s] = (c < nch) ? c : IMAXX;
            if (c < nch) {
                int rows = N - c * CHR; if (rows > CHR) rows = CHR;
                mb_tx(s2u(&mbs[s]), rows * 32);
                bulk_g2s(s2u(&inb[s][0]), (const void*)(X + (size_t)c * CHR * 16), rows * 32, s2u(&mbs[s]), plast);
            }
        }
    }
    __syncthreads();

    float S = 0.f; u64 Wa[8];
#pragma unroll
    for (int k = 0; k < 8; k++) Wa[k] = 0ull;

    for (int k = 0; ; k++) {
        int s = k % 3;
        int c = sq[s];
        if (c == IMAXX) break;
        unsigned ph = (unsigned)((k / 3) & 1);
        mb_wait(s2u(&mbs[s]), ph);

        int row0 = c * CHR;
        int rows = N - row0; if (rows > CHR) rows = CHR;
        bool ok0 = t < rows, ok1 = t + BLOCK < rows;
        u64 x0[8], x1[8];
        if (ok0) lds_row_h(s2u(&inb[s][0]), t, x0); else { for (int i = 0; i < 8; i++) x0[i] = 0ull; }
        if (ok1) lds_row_h(s2u(&inb[s][0]), t + BLOCK, x1); else { for (int i = 0; i < 8; i++) x1[i] = 0ull; }

        float l00 = 0.f, l01 = 0.f, l10 = 0.f, l11 = 0.f;
#pragma unroll
        for (int j = 0; j < 16; j++) {
            u64 a0 = 0ull, a1 = 0ull;
#pragma unroll
            for (int dd = 0; dd < 4; dd++) {
                ulonglong2 w = sWr[j * 4 + dd];
                a0 = F2(x0[2 * dd], w.x, a0); a0 = F2(x0[2 * dd + 1], w.y, a0);
                a1 = F2(x1[2 * dd], w.x, a1); a1 = F2(x1[2 * dd + 1], w.y, a1);
            }
            float2 u0 = unpack2(a0), u1 = unpack2(a1); float vj = sV[j], qj = sQ[j];
            float v0 = vj * ftanh(u0.x + u0.y + qj), v1 = vj * ftanh(u1.x + u1.y + qj);
            if (j & 1) { l01 += v0; l11 += v1; } else { l00 += v0; l10 += v1; }
        }
        if (ok0) {
            float w = __expf(l00 + l01); S += w; u64 wp = pack2(w, w);
#pragma unroll
            for (int kk = 0; kk < 8; kk++) Wa[kk] = F2(wp, x0[kk], Wa[kk]);
        }
        if (ok1) {
            float w = __expf(l10 + l11); S += w; u64 wp = pack2(w, w);
#pragma unroll
            for (int kk = 0; kk < 8; kk++) Wa[kk] = F2(wp, x1[kk], Wa[kk]);
        }
        __syncthreads();
        if (t == 0) {
            int cn = atomicAdd(sctr, 1);
            sq[s] = (cn < nch) ? cn : IMAXX;
            if (cn < nch) {
                int rn = N - cn * CHR; if (rn > CHR) rn = CHR;
                mb_tx(s2u(&mbs[s]), rn * 32);
                bulk_g2s(s2u(&inb[s][0]), (const void*)(X + (size_t)cn * CHR * 16), rn * 32, s2u(&mbs[s]), plast);
            }
        }
    }

    float acc[17]; acc[0] = S;
#pragma unroll
    for (int k = 0; k < 8; k++) { float2 u = unpack2(Wa[k]); acc[1 + 2 * k] = u.x; acc[2 + 2 * k] = u.y; }
    redu17(acc, part);
    __syncthreads();
    __shared__ int lastb;
    if (t == 0) { __threadfence(); lastb = (atomicAdd(&g_c2, 1) == NBL - 1); }
    __syncthreads();
    if (lastb) {
        fin_g(t, &inb[0][0], BJL, NBML, g_ejs, g2W, g2b, g_g2, &g_c2);
        if (t == 0) { g_s3 = 0; g_s4 = 0; }
    }
}

// ================= passes 2 & 4: pointer logits over fp16 E (2 rows/thread) =================
__global__ void __launch_bounds__(BLOCK, 6) k_arg(
    int which, int N,
    const float* __restrict__ Wr, const float* __restrict__ V,
    const float* __restrict__ Wq, const float* __restrict__ bq,
    const void* __restrict__ maskp, int nmask, float* __restrict__ out,
    const float* __restrict__ jobsX,
    const float* __restrict__ jW1, const float* __restrict__ jb1,
    const float* __restrict__ jW2, const float* __restrict__ jb2)
{
    __shared__ __align__(128) char inb[3][CBR];
    __shared__ u64 mbs[3];
    __shared__ int sq[3];
    __shared__ ulonglong2 sWr[64];
    __shared__ float sV[16], sQ[16];
    __shared__ int smk;

    int t = threadIdx.x;
    const u16* X = which ? g_Em : g_Ej;
    const float* qs = which ? g_g2 : g_g1;
    int* cnt = which ? &g_c3 : &g_c1;
    int* sctr = which ? &g_s5 : &g_s2;

    u64 plast = pol_evict_last();

    if (t == 0) smk = 0;
    if (t < 64) sWr[t] = ((const ulonglong2*)Wr)[t];
    if (t < 16) {
        sV[t] = V[t];
        float q = bq[t];
#pragma unroll
        for (int d = 0; d < 16; d++) q += qs[d] * Wq[t * 16 + d];
        sQ[t] = q;
    }
    if (t == 0) {
#pragma unroll
        for (int s = 0; s < 3; s++) mb_init(s2u(&mbs[s]), 1);
    }
    __syncthreads();
    if (maskp) {
        int words = nmask >> 2; if (words > 4096) words = 4096;
        int f = 0;
        for (int i = t; i < words; i += BLOCK) {
            unsigned w = ((const unsigned*)maskp)[i];
            if (w != 0u && w != 1u && w != 0x3F800000u) f = 1;
        }
        if (f) atomicOr(&smk, 1);
    }
    __syncthreads();
    int mk = smk;

    int nch = (N + CHR - 1) / CHR;
    if (t == 0) {
#pragma unroll
        for (int s = 0; s < 3; s++) {
            int c = atomicAdd(sctr, 1);
            sq[s] = (c < nch) ? c : IMAXX;
            if (c < nch) {
                int rows = N - c * CHR; if (rows > CHR) rows = CHR;
                mb_tx(s2u(&mbs[s]), rows * 32);
                bulk_g2s(s2u(&inb[s][0]), (const void*)(X + (size_t)c * CHR * 16), rows * 32, s2u(&mbs[s]), plast);
            }
        }
    }
    __syncthreads();

    float best = -3e38f, sum = 0.f; int bi = IMAXX;
    for (int k = 0; ; k++) {
        int s = k % 3;
        int c = sq[s];
        if (c == IMAXX) break;
        unsigned ph = (unsigned)((k / 3) & 1);
        mb_wait(s2u(&mbs[s]), ph);

        int row0 = c * CHR;
        int rows = N - row0; if (rows > CHR) rows = CHR;
        bool ok0 = t < rows, ok1 = t + BLOCK < rows;
        u64 x0[8], x1[8];
        if (ok0) lds_row_h(s2u(&inb[s][0]), t, x0); else { for (int i = 0; i < 8; i++) x0[i] = 0ull; }
        if (ok1) lds_row_h(s2u(&inb[s][0]), t + BLOCK, x1); else { for (int i = 0; i < 8; i++) x1[i] = 0ull; }

        float l00 = 0.f, l01 = 0.f, l10 = 0.f, l11 = 0.f;
#pragma unroll
        for (int j = 0; j < 16; j++) {
            u64 a0 = 0ull, a1 = 0ull;
#pragma unroll
            for (int dd = 0; dd < 4; dd++) {
                ulonglong2 w = sWr[j * 4 + dd];
                a0 = F2(x0[2 * dd], w.x, a0); a0 = F2(x0[2 * dd + 1], w.y, a0);
                a1 = F2(x1[2 * dd], w.x, a1); a1 = F2(x1[2 * dd + 1], w.y, a1);
            }
            float2 u0 = unpack2(a0), u1 = unpack2(a1); float vj = sV[j], qj = sQ[j];
            float v0 = vj * ftanh(u0.x + u0.y + qj), v1 = vj * ftanh(u1.x + u1.y + qj);
            if (j & 1) { l01 += v0; l11 += v1; } else { l00 += v0; l10 += v1; }
        }
#pragma unroll
        for (int r = 0; r < 2; r++) {
            bool ok = r ? ok1 : ok0;
            if (ok) {
                float l = r ? (l10 + l11) : (l00 + l01);
                int row = row0 + t + r * BLOCK;
                bool pass = true;
                if (maskp) {
                    if (mk) pass = ((const unsigned char*)maskp)[row] != 0;
                    else    pass = ((const unsigned*)maskp)[row] != 0u;
                }
                if (pass) {
                    sum += __expf(l);
                    if (l > best) { best = l; bi = row; }
                }
            }
        }
        __syncthreads();
        if (t == 0) {
            int cn = atomicAdd(sctr, 1);
            sq[s] = (cn < nch) ? cn : IMAXX;
            if (cn < nch) {
                int rn = N - cn * CHR; if (rn > CHR) rn = CHR;
                mb_tx(s2u(&mbs[s]), rn * 32);
                bulk_g2s(s2u(&inb[s][0]), (const void*)(X + (size_t)cn * CHR * 16), rn * 32, s2u(&mbs[s]), plast);
            }
        }
    }
#pragma unroll
    for (int of = 16; of > 0; of >>= 1) {
        float ov = __shfl_down_sync(0xffffffffu, best, of);
        int   oi = __shfl_down_sync(0xffffffffu, bi, of);
        sum += __shfl_down_sync(0xffffffffu, sum, of);
        if (ov > best || (ov == best && oi < bi)) { best = ov; bi = oi; }
    }
    __shared__ float wv[4], ws[4]; __shared__ int wi[4];
    int lane = t & 31, wid = t >> 5;
    if (lane == 0) { wv[wid] = best; wi[wid] = bi; ws[wid] = sum; }
    __syncthreads();
    if (t == 0) {
        float v = wv[0]; int ix = wi[0]; float s = ws[0];
#pragma unroll
        for (int w = 1; w < 4; w++) {
            if (wv[w] > v || (wv[w] == v && wi[w] < ix)) { v = wv[w]; ix = wi[w]; }
            s += ws[w];
        }
        g_aV[blockIdx.x] = v; g_aI[blockIdx.x] = ix; g_aS[blockIdx.x] = s;
    }
    __syncthreads();
    __shared__ int lastb;
    if (t == 0) { __threadfence(); lastb = (atomicAdd(cnt, 1) == NBA - 1); }
    __syncthreads();
    if (lastb) {
        fin_arg(t, which, out, cnt, jobsX, jW1, jb1, jW2, jb2);
        if (t == 0) { if (which) g_s5 = 0; else g_s2 = 0; }
    }
}

extern "C" void kernel_launch(void* const* d_in, const int* in_sizes, int n_in,
                              void* d_out, int out_size) {
    const float* jobs  = (const float*)d_in[0];
    const float* machs = (const float*)d_in[1];
    const void*  mask  = d_in[2];
    const float *jW1=(const float*)d_in[3], *jb1=(const float*)d_in[4], *jW2=(const float*)d_in[5], *jb2=(const float*)d_in[6];
    const float *mW1=(const float*)d_in[7], *mb1=(const float*)d_in[8], *mW2=(const float*)d_in[9], *mb2=(const float*)d_in[10];
    const float *ajWq=(const float*)d_in[11], *ajbq=(const float*)d_in[12], *ajWr=(const float*)d_in[13], *ajV=(const float*)d_in[14];
    const float *amWq=(const float*)d_in[15], *ambq=(const float*)d_in[16], *amWr=(const float*)d_in[17], *amV=(const float*)d_in[18];
    const float *jaWq=(const float*)d_in[19], *jabq=(const float*)d_in[20], *jaWr=(const float*)d_in[21], *jaV=(const float*)d_in[22];
    const float *maWq=(const float*)d_in[23], *mabq=(const float*)d_in[24], *maWr=(const float*)d_in[25], *maV=(const float*)d_in[26];
    const float *g1W=(const float*)d_in[27], *g1b=(const float*)d_in[28];
    const float *g2W=(const float*)d_in[29], *g2b=(const float*)d_in[30];
    const float *lastj=(const float*)d_in[31];
    int Nj = in_sizes[0] / 16;
    int Nm = in_sizes[1] / 16;
    float* out = (float*)d_out;

    k_emb<<<NBE, BLOCK>>>(jobs, machs, Nj, Nm, jW1, jb1, jW2, jb2, mW1, mb1, mW2, mb2,
                          ajWr, ajV, ajWq, ajbq, amWr, amV, amWq, ambq, lastj, g1W, g1b);
    k_arg<<<NBA, BLOCK>>>(0, Nj, jaWr, jaV, jaWq, jabq, mask, in_sizes[2], out,
                          jobs, jW1, jb1, jW2, jb2);
    k_gl <<<NBL, BLOCK>>>(Nj, Nm, ajWr, ajV, ajWq, ajbq, amWr, amV, amWq, ambq, g2W, g2b);
    k_arg<<<NBA, BLOCK>>>(1, Nm, maWr, maV, maWq, mabq, nullptr, 0, out,
                          nullptr, nullptr, nullptr, nullptr, nullptr);
    (void)n_in; (void)out_size;
}